// round 12
// baseline (speedup 1.0000x reference)
#include <cuda_runtime.h>
#include <cuda_bf16.h>
#include <cstdint>
#include <math.h>

// ---------------------------------------------------------------------------
// SchnetConv — R11 (persistent edge CTAs, mma.sync m16n8k16 bf16 hi/lo 3-term,
// 16 rows/warp, red.global.v2 epilogue) + L2 prefetch of next tile's
// bf/eh/src/dst working set.
// ---------------------------------------------------------------------------

#define Dc       64
#define Rc       128
#define TILE_E   128
#define TILE_N   64
#define WST      68
#define N_MAX    100000
#define EDGE_GRID 296      // 2 CTAs/SM x 148 SMs

__device__ float g_s[(size_t)N_MAX * Dc];
__device__ float g_cnt[N_MAX];
// fragment-ordered weight image: B1 [8ks][8nt][32lane] uint4{hix,hiy,lox,loy} =32KB,
// then B2 [4ks][8nt][32lane] uint4 = 16KB
__device__ __align__(16) unsigned char g_Bimg[49152];

// SMEM layout (bytes)
#define OFF_B1    0
#define OFF_B2    32768
#define OFF_A2HI  49152     // 8 warps x 2048B (16 rows x 128B, swizzled)
#define OFF_A2LO  65536
#define OFF_BIAS  81920     // b1[64], b2[64]
#define SMEM_EDGE 82432

// ---- helpers ---------------------------------------------------------------
__device__ __forceinline__ float ssp_f(float x) {
    float e = __expf(-fabsf(x));
    return fmaxf(x, 0.0f) + log1pf(e) - 0.69314718055994531f;
}
__device__ __forceinline__ uint32_t swz(uint32_t off) { return off ^ ((off >> 3) & 0x70); }
__device__ __forceinline__ int wswz(int j) { return j + (((j >> 5) & 1) << 2); }

__device__ __forceinline__ uint32_t smem_u32(const void* p) {
    uint32_t a;
    asm("{ .reg .u64 t; cvta.to.shared.u64 t, %1; cvt.u32.u64 %0, t; }" : "=r"(a) : "l"(p));
    return a;
}
__device__ __forceinline__ void pf_l2(const void* p) {
    asm volatile("prefetch.global.L2 [%0];" :: "l"(p));
}
// x = hi + lo (bf16 each); packs (x0 -> low half, x1 -> high half)
__device__ __forceinline__ void split2(float x0, float x1, uint32_t& hi, uint32_t& lo) {
    asm("cvt.rn.bf16x2.f32 %0, %1, %2;" : "=r"(hi) : "f"(x1), "f"(x0));
    float h0 = __uint_as_float(hi << 16);
    float h1 = __uint_as_float(hi & 0xffff0000u);
    asm("cvt.rn.bf16x2.f32 %0, %1, %2;" : "=r"(lo) : "f"(x1 - h1), "f"(x0 - h0));
}
__device__ __forceinline__ void mma16816(float* c, const uint32_t* a, uint32_t b0, uint32_t b1) {
    asm volatile(
        "mma.sync.aligned.m16n8k16.row.col.f32.bf16.bf16.f32 "
        "{%0,%1,%2,%3}, {%4,%5,%6,%7}, {%8,%9}, {%0,%1,%2,%3};"
        : "+f"(c[0]), "+f"(c[1]), "+f"(c[2]), "+f"(c[3])
        : "r"(a[0]), "r"(a[1]), "r"(a[2]), "r"(a[3]), "r"(b0), "r"(b1));
}
__device__ __forceinline__ void ldmx4(uint32_t* r, uint32_t addr) {
    asm volatile("ldmatrix.sync.aligned.m8n8.x4.shared.b16 {%0,%1,%2,%3}, [%4];"
        : "=r"(r[0]), "=r"(r[1]), "=r"(r[2]), "=r"(r[3]) : "r"(addr));
}

// ---------------------------------------------------------------------------
__global__ void zero_kernel(int n_nodes) {
    int i = blockIdx.x * 256 + threadIdx.x;
    int t4 = n_nodes * (Dc / 4);
    if (i < t4) ((float4*)g_s)[i] = make_float4(0.f, 0.f, 0.f, 0.f);
    if (i < n_nodes) g_cnt[i] = 0.0f;
}

// Build fragment-ordered hi/lo weight image. 2048 B1 entries, 1024 B2 entries.
__global__ void prep_kernel(const float* __restrict__ W1, const float* __restrict__ W2) {
    int i = blockIdx.x * 256 + threadIdx.x;
    if (i < 2048) {   // B1: idx = (ks*8+nt)*32+lane
        int lane = i & 31, nt = (i >> 5) & 7, ks = i >> 8;
        int tid4 = lane & 3, g = lane >> 2;
        int k0 = ks * 16 + tid4 * 2;
        int n  = nt * 8 + g;
        float e00 = W1[(k0    ) * Dc + n], e01 = W1[(k0 + 1) * Dc + n];
        float e10 = W1[(k0 + 8) * Dc + n], e11 = W1[(k0 + 9) * Dc + n];
        uint32_t hx, lx, hy, ly;
        split2(e00, e01, hx, lx);
        split2(e10, e11, hy, ly);
        uint4 v; v.x = hx; v.y = hy; v.z = lx; v.w = ly;
        ((uint4*)g_Bimg)[i] = v;
    }
    if (i < 1024) {   // B2
        int lane = i & 31, nt = (i >> 5) & 7, ks = i >> 8;
        int tid4 = lane & 3, g = lane >> 2;
        int k0 = ks * 16 + tid4 * 2;
        int n  = nt * 8 + g;
        float e00 = W2[(k0    ) * Dc + n], e01 = W2[(k0 + 1) * Dc + n];
        float e10 = W2[(k0 + 8) * Dc + n], e11 = W2[(k0 + 9) * Dc + n];
        uint32_t hx, lx, hy, ly;
        split2(e00, e01, hx, lx);
        split2(e10, e11, hy, ly);
        uint4 v; v.x = hx; v.y = hy; v.z = lx; v.w = ly;
        ((uint4*)(g_Bimg + OFF_B2))[i] = v;
    }
}

// ---------------------------------------------------------------------------
// Persistent edge kernel: weights staged once, sync-free warp-local tile
// loop, next-tile L2 prefetch.
// ---------------------------------------------------------------------------
__global__ __launch_bounds__(256, 2)
void edge_kernel(const float* __restrict__ bf, const float* __restrict__ eh,
                 const float* __restrict__ nh, const int* __restrict__ src,
                 const int* __restrict__ dst,
                 const float* __restrict__ b1, const float* __restrict__ b2,
                 int E, int ntiles)
{
    extern __shared__ unsigned char smx[];
    const uint32_t sb = smem_u32(smx);
    const int t = threadIdx.x, w = t >> 5, lane = t & 31;
    const int g = lane >> 2, tid4 = lane & 3;

    // one-time stage: weight fragments (48KB) + biases
    {
        const uint4* gi = (const uint4*)g_Bimg;
        uint4* s = (uint4*)smx;
        for (int i = t; i < 3072; i += 256) s[i] = gi[i];
        float* sbias = (float*)(smx + OFF_BIAS);
        if (t < Dc) sbias[t] = b1[t];
        else if (t < 2 * Dc) sbias[t] = b2[t - Dc];
    }
    __syncthreads();

    const float* sb1 = (const float*)(smx + OFF_BIAS);
    const float* sb2 = sb1 + Dc;
    const uint32_t aHbase = sb + OFF_A2HI + w * 2048;
    const uint32_t aLbase = sb + OFF_A2LO + w * 2048;

    for (int tile = blockIdx.x; tile < ntiles; tile += gridDim.x) {
        const int e0 = tile * TILE_E + w * 16;   // warp's first edge row

        // ---- L2 prefetch for the NEXT tile (full tile of lead time) ----
        {
            const int ntile = tile + gridDim.x;
            if (ntile < ntiles) {
                const int ne0 = ntile * TILE_E + w * 16;
                // bf rows (512B each): 4 lanes (tid4) x 128B cover one row
                int r0 = min(ne0 + g,     E - 1);
                int r1 = min(ne0 + g + 8, E - 1);
                pf_l2((const char*)(bf + (size_t)r0 * Rc) + tid4 * 128);
                pf_l2((const char*)(bf + (size_t)r1 * Rc) + tid4 * 128);
                // eh rows (256B each): tid4 0-1 -> row r0, tid4 2-3 -> row r1
                int re = min(ne0 + g + (tid4 >> 1) * 8, E - 1);
                pf_l2((const char*)(eh + (size_t)re * Dc) + (tid4 & 1) * 128);
                // src/dst lines for the whole next tile (512B each): warp 0
                if (w == 0 && lane < 8) {
                    int base = min(ntile * TILE_E, E - 1);
                    const int* p = (lane < 4) ? (src + base) : (dst + base);
                    pf_l2((const char*)p + (lane & 3) * 128);
                }
            }
        }

        // clamp row pointers (rows may exceed E on the ragged tail)
        const int er0 = min(e0 + g,     E - 1);
        const int er1 = min(e0 + g + 8, E - 1);
        const bool v0 = (e0 + g)     < E;
        const bool v1 = (e0 + g + 8) < E;
        const float* p0 = bf + (size_t)er0 * Rc;
        const float* p1 = bf + (size_t)er1 * Rc;

        float acc[8][4];
#pragma unroll
        for (int nt = 0; nt < 8; ++nt)
#pragma unroll
            for (int q = 0; q < 4; ++q) acc[nt][q] = 0.f;

        // ---- GEMM1: f1raw = bf @ W1, K=128 (8 k-steps), N=64 (8 n-tiles) ----
#pragma unroll
        for (int ks = 0; ks < 8; ++ks) {
            const int k0 = ks * 16 + tid4 * 2;
            float2 x00 = *(const float2*)(p0 + k0);
            float2 x10 = *(const float2*)(p1 + k0);
            float2 x01 = *(const float2*)(p0 + k0 + 8);
            float2 x11 = *(const float2*)(p1 + k0 + 8);
            uint32_t aH[4], aL[4];
            split2(x00.x, x00.y, aH[0], aL[0]);
            split2(x10.x, x10.y, aH[1], aL[1]);
            split2(x01.x, x01.y, aH[2], aL[2]);
            split2(x11.x, x11.y, aH[3], aL[3]);
            const uint4* Bp = (const uint4*)(smx + OFF_B1) + (ks * 8) * 32 + lane;
#pragma unroll
            for (int nt = 0; nt < 8; ++nt) {
                uint4 bb = Bp[nt * 32];
                mma16816(acc[nt], aH, bb.x, bb.y);   // Ah*Bh
                mma16816(acc[nt], aH, bb.z, bb.w);   // Ah*Bl
                mma16816(acc[nt], aL, bb.x, bb.y);   // Al*Bh
            }
        }

        // ---- bias + ssp + hi/lo split -> per-warp A2 strips (swizzled) ----
#pragma unroll
        for (int nt = 0; nt < 8; ++nt) {
            int n = nt * 8 + tid4 * 2;
            float f0 = ssp_f(acc[nt][0] + sb1[n]);
            float f1 = ssp_f(acc[nt][1] + sb1[n + 1]);
            float f2 = ssp_f(acc[nt][2] + sb1[n]);
            float f3 = ssp_f(acc[nt][3] + sb1[n + 1]);
            uint32_t h01, l01, h23, l23;
            split2(f0, f1, h01, l01);
            split2(f2, f3, h23, l23);
            uint32_t o0 = swz((uint32_t)g       * 128 + (uint32_t)n * 2);
            uint32_t o1 = swz((uint32_t)(g + 8) * 128 + (uint32_t)n * 2);
            asm volatile("st.shared.b32 [%0], %1;" :: "r"(aHbase + o0), "r"(h01) : "memory");
            asm volatile("st.shared.b32 [%0], %1;" :: "r"(aHbase + o1), "r"(h23) : "memory");
            asm volatile("st.shared.b32 [%0], %1;" :: "r"(aLbase + o0), "r"(l01) : "memory");
            asm volatile("st.shared.b32 [%0], %1;" :: "r"(aLbase + o1), "r"(l23) : "memory");
#pragma unroll
            for (int q = 0; q < 4; ++q) acc[nt][q] = 0.f;
        }
        __syncwarp();

        // ---- GEMM2: f2raw = f1 @ W2, K=64 (4 k-steps) ----
        {
            const int lrow = lane & 15, half = lane >> 4;
#pragma unroll
            for (int ks = 0; ks < 4; ++ks) {
                uint32_t off = swz((uint32_t)lrow * 128 + (uint32_t)ks * 32 + (uint32_t)half * 16);
                uint32_t aH[4], aL[4];
                ldmx4(aH, aHbase + off);
                ldmx4(aL, aLbase + off);
                const uint4* Bp = (const uint4*)(smx + OFF_B2) + (ks * 8) * 32 + lane;
#pragma unroll
                for (int nt = 0; nt < 8; ++nt) {
                    uint4 bb = Bp[nt * 32];
                    mma16816(acc[nt], aH, bb.x, bb.y);
                    mma16816(acc[nt], aH, bb.z, bb.w);
                    mma16816(acc[nt], aL, bb.x, bb.y);
                }
            }
        }
        __syncwarp();   // A2 strip reads complete before next tile overwrites

        // ---- epilogue: m = f2 * eh * nh[src]; red.global.v2 to g_s ----
        int sv0 = 0, dv0 = 0, sv1 = 0, dv1 = 0;
        if (v0) { sv0 = src[e0 + g];     dv0 = dst[e0 + g]; }
        if (v1) { sv1 = src[e0 + g + 8]; dv1 = dst[e0 + g + 8]; }
        if (tid4 == 0) {
            if (v0) atomicAdd(&g_cnt[dv0], 1.0f);
            if (v1) atomicAdd(&g_cnt[dv1], 1.0f);
        }
#pragma unroll
        for (int nt = 0; nt < 8; ++nt) {
            int n = nt * 8 + tid4 * 2;
            if (v0) {
                float f0 = ssp_f(acc[nt][0] + sb2[n]);
                float f1 = ssp_f(acc[nt][1] + sb2[n + 1]);
                float2 ev = *(const float2*)&eh[(size_t)(e0 + g) * Dc + n];
                float2 nv = *(const float2*)&nh[(size_t)sv0 * Dc + n];
                float m0 = f0 * ev.x * nv.x;
                float m1 = f1 * ev.y * nv.y;
                float* gp = &g_s[(size_t)dv0 * Dc + n];
                asm volatile("red.global.add.v2.f32 [%0], {%1, %2};"
                             :: "l"(gp), "f"(m0), "f"(m1) : "memory");
            }
            if (v1) {
                float f2 = ssp_f(acc[nt][2] + sb2[n]);
                float f3 = ssp_f(acc[nt][3] + sb2[n + 1]);
                float2 ev = *(const float2*)&eh[(size_t)(e0 + g + 8) * Dc + n];
                float2 nv = *(const float2*)&nh[(size_t)sv1 * Dc + n];
                float m2 = f2 * ev.x * nv.x;
                float m3 = f3 * ev.y * nv.y;
                float* gp = &g_s[(size_t)dv1 * Dc + n];
                asm volatile("red.global.add.v2.f32 [%0], {%1, %2};"
                             :: "l"(gp), "f"(m2), "f"(m3) : "memory");
            }
        }
    }
}

// ---------------------------------------------------------------------------
// Node kernel: mean -> MLP3 -> MLP4 (validated R5/R8)
// ---------------------------------------------------------------------------
__global__ __launch_bounds__(256)
void node_kernel(const float* __restrict__ W3, const float* __restrict__ b3,
                 const float* __restrict__ W4, const float* __restrict__ b4,
                 float* __restrict__ out, int N)
{
    extern __shared__ float sm[];
    float* W3s  = sm;
    float* W4s  = W3s + Dc * WST;
    float* b3s  = W4s + Dc * WST;
    float* b4s  = b3s + Dc;
    float* cS   = b4s + Dc;
    float* aggS = cS + TILE_N;
    float* h1S  = aggS + TILE_N * WST;

    const int t      = threadIdx.x;
    const int n_base = blockIdx.x * TILE_N;

    for (int i = t; i < Dc * Dc; i += 256) {
        int k = i >> 6, j = i & 63;
        int js = wswz(j);
        W3s[k * WST + js] = W3[i];
        W4s[k * WST + js] = W4[i];
    }
    if (t < Dc) { b3s[t] = b3[t]; b4s[t] = b4[t]; }
    if (t < TILE_N) {
        int n = n_base + t;
        float c = (n < N) ? g_cnt[n] : 0.0f;
        cS[t] = (c > 0.0f) ? (1.0f / c) : 0.0f;
    }
    __syncthreads();

    for (int i4 = t; i4 < TILE_N * (Dc / 4); i4 += 256) {
        int nl = i4 >> 4;
        int k4 = (i4 & 15) << 2;
        int n  = n_base + nl;
        float4 v = make_float4(0.f, 0.f, 0.f, 0.f);
        if (n < N) {
            v = *(const float4*)&g_s[(size_t)n * Dc + k4];
            float inv = cS[nl];
            v.x *= inv; v.y *= inv; v.z *= inv; v.w *= inv;
        }
        *(float4*)&aggS[nl * WST + k4] = v;
    }
    __syncthreads();

    const int tj = t & 7;
    const int tn = t >> 3;
    const int j0 = tj << 3;
    const int jo = wswz(j0);
    const int n0 = tn << 1;

    float acc[2][8];
#pragma unroll
    for (int a = 0; a < 2; ++a)
#pragma unroll
        for (int b = 0; b < 8; ++b) acc[a][b] = 0.f;

#pragma unroll 8
    for (int k = 0; k < Dc; ++k) {
        float4 wA = *(const float4*)&W3s[k * WST + jo];
        float4 wB = *(const float4*)&W3s[k * WST + jo + 4];
        float w[8] = {wA.x, wA.y, wA.z, wA.w, wB.x, wB.y, wB.z, wB.w};
        float x0 = aggS[(n0 + 0) * WST + k];
        float x1 = aggS[(n0 + 1) * WST + k];
#pragma unroll
        for (int b = 0; b < 8; ++b) {
            acc[0][b] = fmaf(x0, w[b], acc[0][b]);
            acc[1][b] = fmaf(x1, w[b], acc[1][b]);
        }
    }
#pragma unroll
    for (int a = 0; a < 2; ++a) {
        float h[8];
#pragma unroll
        for (int b = 0; b < 8; ++b) h[b] = ssp_f(acc[a][b] + b3s[j0 + b]);
        *(float4*)&h1S[(n0 + a) * WST + j0]     = make_float4(h[0], h[1], h[2], h[3]);
        *(float4*)&h1S[(n0 + a) * WST + j0 + 4] = make_float4(h[4], h[5], h[6], h[7]);
#pragma unroll
        for (int b = 0; b < 8; ++b) acc[a][b] = 0.f;
    }
    __syncthreads();

#pragma unroll 8
    for (int k = 0; k < Dc; ++k) {
        float4 wA = *(const float4*)&W4s[k * WST + jo];
        float4 wB = *(const float4*)&W4s[k * WST + jo + 4];
        float w[8] = {wA.x, wA.y, wA.z, wA.w, wB.x, wB.y, wB.z, wB.w};
        float x0 = h1S[(n0 + 0) * WST + k];
        float x1 = h1S[(n0 + 1) * WST + k];
#pragma unroll
        for (int b = 0; b < 8; ++b) {
            acc[0][b] = fmaf(x0, w[b], acc[0][b]);
            acc[1][b] = fmaf(x1, w[b], acc[1][b]);
        }
    }
#pragma unroll
    for (int a = 0; a < 2; ++a) {
        int n = n_base + n0 + a;
        if (n < N) {
            float o[8];
#pragma unroll
            for (int b = 0; b < 8; ++b) o[b] = ssp_f(acc[a][b] + b4s[j0 + b]);
            *(float4*)&out[(size_t)n * Dc + j0]     = make_float4(o[0], o[1], o[2], o[3]);
            *(float4*)&out[(size_t)n * Dc + j0 + 4] = make_float4(o[4], o[5], o[6], o[7]);
        }
    }
}

// ---------------------------------------------------------------------------
extern "C" void kernel_launch(void* const* d_in, const int* in_sizes, int n_in,
                              void* d_out, int out_size)
{
    const float* bf  = (const float*)d_in[0];
    const float* eh  = (const float*)d_in[1];
    const float* nh  = (const float*)d_in[2];
    const int*   src = (const int*)  d_in[3];
    const int*   dst = (const int*)  d_in[4];
    const float* W1  = (const float*)d_in[5];
    const float* b1  = (const float*)d_in[6];
    const float* W2  = (const float*)d_in[7];
    const float* b2  = (const float*)d_in[8];
    const float* W3  = (const float*)d_in[9];
    const float* b3  = (const float*)d_in[10];
    const float* W4  = (const float*)d_in[11];
    const float* b4  = (const float*)d_in[12];

    int E = in_sizes[3];
    int N = in_sizes[2] / Dc;

    const int NODE_SMEM = (2 * Dc * WST + 2 * Dc + TILE_N + 2 * TILE_N * WST) * (int)sizeof(float);

    cudaFuncSetAttribute(edge_kernel, cudaFuncAttributeMaxDynamicSharedMemorySize, SMEM_EDGE);
    cudaFuncSetAttribute(node_kernel, cudaFuncAttributeMaxDynamicSharedMemorySize, NODE_SMEM);

    int zero_grid = (N * (Dc / 4) + 255) / 256;
    zero_kernel<<<zero_grid, 256>>>(N);

    prep_kernel<<<8, 256>>>(W1, W2);

    int ntiles = (E + TILE_E - 1) / TILE_E;
    int egrid = ntiles < EDGE_GRID ? ntiles : EDGE_GRID;
    edge_kernel<<<egrid, 256, SMEM_EDGE>>>(bf, eh, nh, src, dst, b1, b2, E, ntiles);

    int node_grid = (N + TILE_N - 1) / TILE_N;
    node_kernel<<<node_grid, 256, NODE_SMEM>>>(W3, b3, W4, b4, (float*)d_out, N);
}

// round 13
// speedup vs baseline: 1.1236x; 1.1236x over previous
#include <cuda_runtime.h>
#include <cuda_bf16.h>
#include <cstdint>
#include <math.h>

// ---------------------------------------------------------------------------
// SchnetConv — R11 edge kernel (persistent CTAs, mma.sync m16n8k16 bf16 hi/lo
// 3-term, 16 rows/warp, red.global.v2 epilogue) + mma node kernel (same
// warp-tile machinery for MLP3/MLP4).
// ---------------------------------------------------------------------------

#define Dc       64
#define Rc       128
#define TILE_E   128
#define N_MAX    100000
#define EDGE_GRID 296      // 2 CTAs/SM x 148 SMs

__device__ float g_s[(size_t)N_MAX * Dc];
__device__ float g_cnt[N_MAX];
// fragment-ordered weight image (uint4{hix,hiy,lox,loy} per (ks,nt,lane)):
// B1 [8ks][8nt][32] = 32KB | B2 [4ks][8nt][32] = 16KB | B3 = 16KB | B4 = 16KB
__device__ __align__(16) unsigned char g_Bimg[81920];

// edge SMEM layout (bytes)
#define OFF_B1    0
#define OFF_B2    32768
#define OFF_A2HI  49152     // 8 warps x 2048B (16 rows x 128B, swizzled)
#define OFF_A2LO  65536
#define OFF_BIAS  81920     // b1[64], b2[64]
#define SMEM_EDGE 82432

// node SMEM layout (bytes)
#define NOFF_B3    0
#define NOFF_B4    16384
#define NOFF_AHI   32768    // 8 warps x 2048B
#define NOFF_ALO   49152
#define NOFF_BIAS  65536    // b3[64], b4[64]
#define SMEM_NODE  66048

// ---- helpers ---------------------------------------------------------------
__device__ __forceinline__ float ssp_f(float x) {
    float e = __expf(-fabsf(x));
    return fmaxf(x, 0.0f) + log1pf(e) - 0.69314718055994531f;
}
__device__ __forceinline__ uint32_t swz(uint32_t off) { return off ^ ((off >> 3) & 0x70); }

__device__ __forceinline__ uint32_t smem_u32(const void* p) {
    uint32_t a;
    asm("{ .reg .u64 t; cvta.to.shared.u64 t, %1; cvt.u32.u64 %0, t; }" : "=r"(a) : "l"(p));
    return a;
}
// x = hi + lo (bf16 each); packs (x0 -> low half, x1 -> high half)
__device__ __forceinline__ void split2(float x0, float x1, uint32_t& hi, uint32_t& lo) {
    asm("cvt.rn.bf16x2.f32 %0, %1, %2;" : "=r"(hi) : "f"(x1), "f"(x0));
    float h0 = __uint_as_float(hi << 16);
    float h1 = __uint_as_float(hi & 0xffff0000u);
    asm("cvt.rn.bf16x2.f32 %0, %1, %2;" : "=r"(lo) : "f"(x1 - h1), "f"(x0 - h0));
}
__device__ __forceinline__ void mma16816(float* c, const uint32_t* a, uint32_t b0, uint32_t b1) {
    asm volatile(
        "mma.sync.aligned.m16n8k16.row.col.f32.bf16.bf16.f32 "
        "{%0,%1,%2,%3}, {%4,%5,%6,%7}, {%8,%9}, {%0,%1,%2,%3};"
        : "+f"(c[0]), "+f"(c[1]), "+f"(c[2]), "+f"(c[3])
        : "r"(a[0]), "r"(a[1]), "r"(a[2]), "r"(a[3]), "r"(b0), "r"(b1));
}
__device__ __forceinline__ void ldmx4(uint32_t* r, uint32_t addr) {
    asm volatile("ldmatrix.sync.aligned.m8n8.x4.shared.b16 {%0,%1,%2,%3}, [%4];"
        : "=r"(r[0]), "=r"(r[1]), "=r"(r[2]), "=r"(r[3]) : "r"(addr));
}

// ---------------------------------------------------------------------------
__global__ void zero_kernel(int n_nodes) {
    int i = blockIdx.x * 256 + threadIdx.x;
    int t4 = n_nodes * (Dc / 4);
    if (i < t4) ((float4*)g_s)[i] = make_float4(0.f, 0.f, 0.f, 0.f);
    if (i < n_nodes) g_cnt[i] = 0.0f;
}

// Build fragment-ordered hi/lo weight images for W1/W2/W3/W4.
__global__ void prep_kernel(const float* __restrict__ W1, const float* __restrict__ W2,
                            const float* __restrict__ W3, const float* __restrict__ W4) {
    int i = blockIdx.x * 256 + threadIdx.x;
    if (i < 2048) {   // B1: idx = (ks*8+nt)*32+lane
        int lane = i & 31, nt = (i >> 5) & 7, ks = i >> 8;
        int tid4 = lane & 3, g = lane >> 2;
        int k0 = ks * 16 + tid4 * 2;
        int n  = nt * 8 + g;
        float e00 = W1[(k0    ) * Dc + n], e01 = W1[(k0 + 1) * Dc + n];
        float e10 = W1[(k0 + 8) * Dc + n], e11 = W1[(k0 + 9) * Dc + n];
        uint32_t hx, lx, hy, ly;
        split2(e00, e01, hx, lx);
        split2(e10, e11, hy, ly);
        uint4 v; v.x = hx; v.y = hy; v.z = lx; v.w = ly;
        ((uint4*)g_Bimg)[i] = v;
    }
    if (i < 1024) {   // B2 / B3 / B4 (all 64x64)
        int lane = i & 31, nt = (i >> 5) & 7, ks = i >> 8;
        int tid4 = lane & 3, g = lane >> 2;
        int k0 = ks * 16 + tid4 * 2;
        int n  = nt * 8 + g;
        const float* Ws[3] = {W2, W3, W4};
        unsigned char* dsts[3] = {g_Bimg + 32768, g_Bimg + 49152, g_Bimg + 65536};
#pragma unroll
        for (int m = 0; m < 3; ++m) {
            const float* W = Ws[m];
            float e00 = W[(k0    ) * Dc + n], e01 = W[(k0 + 1) * Dc + n];
            float e10 = W[(k0 + 8) * Dc + n], e11 = W[(k0 + 9) * Dc + n];
            uint32_t hx, lx, hy, ly;
            split2(e00, e01, hx, lx);
            split2(e10, e11, hy, ly);
            uint4 v; v.x = hx; v.y = hy; v.z = lx; v.w = ly;
            ((uint4*)dsts[m])[i] = v;
        }
    }
}

// ---------------------------------------------------------------------------
// Persistent edge kernel (R11): weights staged once, sync-free warp-local
// loop over 128-edge tiles (8 warps x 16 rows each).
// ---------------------------------------------------------------------------
__global__ __launch_bounds__(256, 2)
void edge_kernel(const float* __restrict__ bf, const float* __restrict__ eh,
                 const float* __restrict__ nh, const int* __restrict__ src,
                 const int* __restrict__ dst,
                 const float* __restrict__ b1, const float* __restrict__ b2,
                 int E, int ntiles)
{
    extern __shared__ unsigned char smx[];
    const uint32_t sb = smem_u32(smx);
    const int t = threadIdx.x, w = t >> 5, lane = t & 31;
    const int g = lane >> 2, tid4 = lane & 3;

    // one-time stage: weight fragments (48KB) + biases
    {
        const uint4* gi = (const uint4*)g_Bimg;
        uint4* s = (uint4*)smx;
        for (int i = t; i < 3072; i += 256) s[i] = gi[i];
        float* sbias = (float*)(smx + OFF_BIAS);
        if (t < Dc) sbias[t] = b1[t];
        else if (t < 2 * Dc) sbias[t] = b2[t - Dc];
    }
    __syncthreads();

    const float* sb1 = (const float*)(smx + OFF_BIAS);
    const float* sb2 = sb1 + Dc;
    const uint32_t aHbase = sb + OFF_A2HI + w * 2048;
    const uint32_t aLbase = sb + OFF_A2LO + w * 2048;

    for (int tile = blockIdx.x; tile < ntiles; tile += gridDim.x) {
        const int e0 = tile * TILE_E + w * 16;   // warp's first edge row

        const int er0 = min(e0 + g,     E - 1);
        const int er1 = min(e0 + g + 8, E - 1);
        const bool v0 = (e0 + g)     < E;
        const bool v1 = (e0 + g + 8) < E;
        const float* p0 = bf + (size_t)er0 * Rc;
        const float* p1 = bf + (size_t)er1 * Rc;

        float acc[8][4];
#pragma unroll
        for (int nt = 0; nt < 8; ++nt)
#pragma unroll
            for (int q = 0; q < 4; ++q) acc[nt][q] = 0.f;

        // ---- GEMM1: f1raw = bf @ W1, K=128 (8 k-steps), N=64 (8 n-tiles) ----
#pragma unroll
        for (int ks = 0; ks < 8; ++ks) {
            const int k0 = ks * 16 + tid4 * 2;
            float2 x00 = *(const float2*)(p0 + k0);
            float2 x10 = *(const float2*)(p1 + k0);
            float2 x01 = *(const float2*)(p0 + k0 + 8);
            float2 x11 = *(const float2*)(p1 + k0 + 8);
            uint32_t aH[4], aL[4];
            split2(x00.x, x00.y, aH[0], aL[0]);
            split2(x10.x, x10.y, aH[1], aL[1]);
            split2(x01.x, x01.y, aH[2], aL[2]);
            split2(x11.x, x11.y, aH[3], aL[3]);
            const uint4* Bp = (const uint4*)(smx + OFF_B1) + (ks * 8) * 32 + lane;
#pragma unroll
            for (int nt = 0; nt < 8; ++nt) {
                uint4 bb = Bp[nt * 32];
                mma16816(acc[nt], aH, bb.x, bb.y);   // Ah*Bh
                mma16816(acc[nt], aH, bb.z, bb.w);   // Ah*Bl
                mma16816(acc[nt], aL, bb.x, bb.y);   // Al*Bh
            }
        }

        // ---- bias + ssp + hi/lo split -> per-warp A2 strips (swizzled) ----
#pragma unroll
        for (int nt = 0; nt < 8; ++nt) {
            int n = nt * 8 + tid4 * 2;
            float f0 = ssp_f(acc[nt][0] + sb1[n]);
            float f1 = ssp_f(acc[nt][1] + sb1[n + 1]);
            float f2 = ssp_f(acc[nt][2] + sb1[n]);
            float f3 = ssp_f(acc[nt][3] + sb1[n + 1]);
            uint32_t h01, l01, h23, l23;
            split2(f0, f1, h01, l01);
            split2(f2, f3, h23, l23);
            uint32_t o0 = swz((uint32_t)g       * 128 + (uint32_t)n * 2);
            uint32_t o1 = swz((uint32_t)(g + 8) * 128 + (uint32_t)n * 2);
            asm volatile("st.shared.b32 [%0], %1;" :: "r"(aHbase + o0), "r"(h01) : "memory");
            asm volatile("st.shared.b32 [%0], %1;" :: "r"(aHbase + o1), "r"(h23) : "memory");
            asm volatile("st.shared.b32 [%0], %1;" :: "r"(aLbase + o0), "r"(l01) : "memory");
            asm volatile("st.shared.b32 [%0], %1;" :: "r"(aLbase + o1), "r"(l23) : "memory");
#pragma unroll
            for (int q = 0; q < 4; ++q) acc[nt][q] = 0.f;
        }
        __syncwarp();

        // ---- GEMM2: f2raw = f1 @ W2, K=64 (4 k-steps) ----
        {
            const int lrow = lane & 15, half = lane >> 4;
#pragma unroll
            for (int ks = 0; ks < 4; ++ks) {
                uint32_t off = swz((uint32_t)lrow * 128 + (uint32_t)ks * 32 + (uint32_t)half * 16);
                uint32_t aH[4], aL[4];
                ldmx4(aH, aHbase + off);
                ldmx4(aL, aLbase + off);
                const uint4* Bp = (const uint4*)(smx + OFF_B2) + (ks * 8) * 32 + lane;
#pragma unroll
                for (int nt = 0; nt < 8; ++nt) {
                    uint4 bb = Bp[nt * 32];
                    mma16816(acc[nt], aH, bb.x, bb.y);
                    mma16816(acc[nt], aH, bb.z, bb.w);
                    mma16816(acc[nt], aL, bb.x, bb.y);
                }
            }
        }
        __syncwarp();   // A2 strip reads complete before next tile overwrites

        // ---- epilogue: m = f2 * eh * nh[src]; red.global.v2 to g_s ----
        int sv0 = 0, dv0 = 0, sv1 = 0, dv1 = 0;
        if (v0) { sv0 = src[e0 + g];     dv0 = dst[e0 + g]; }
        if (v1) { sv1 = src[e0 + g + 8]; dv1 = dst[e0 + g + 8]; }
        if (tid4 == 0) {
            if (v0) atomicAdd(&g_cnt[dv0], 1.0f);
            if (v1) atomicAdd(&g_cnt[dv1], 1.0f);
        }
#pragma unroll
        for (int nt = 0; nt < 8; ++nt) {
            int n = nt * 8 + tid4 * 2;
            if (v0) {
                float f0 = ssp_f(acc[nt][0] + sb2[n]);
                float f1 = ssp_f(acc[nt][1] + sb2[n + 1]);
                float2 ev = *(const float2*)&eh[(size_t)(e0 + g) * Dc + n];
                float2 nv = *(const float2*)&nh[(size_t)sv0 * Dc + n];
                float m0 = f0 * ev.x * nv.x;
                float m1 = f1 * ev.y * nv.y;
                float* gp = &g_s[(size_t)dv0 * Dc + n];
                asm volatile("red.global.add.v2.f32 [%0], {%1, %2};"
                             :: "l"(gp), "f"(m0), "f"(m1) : "memory");
            }
            if (v1) {
                float f2 = ssp_f(acc[nt][2] + sb2[n]);
                float f3 = ssp_f(acc[nt][3] + sb2[n + 1]);
                float2 ev = *(const float2*)&eh[(size_t)(e0 + g + 8) * Dc + n];
                float2 nv = *(const float2*)&nh[(size_t)sv1 * Dc + n];
                float m2 = f2 * ev.x * nv.x;
                float m3 = f3 * ev.y * nv.y;
                float* gp = &g_s[(size_t)dv1 * Dc + n];
                asm volatile("red.global.add.v2.f32 [%0], {%1, %2};"
                             :: "l"(gp), "f"(m2), "f"(m3) : "memory");
            }
        }
    }
}

// ---------------------------------------------------------------------------
// Persistent mma node kernel: agg = g_s*inv_cnt -> MLP3 -> MLP4 -> out.
// Same warp-tile machinery as the edge kernel (16 nodes/warp, 128/tile).
// ---------------------------------------------------------------------------
__global__ __launch_bounds__(256, 2)
void node_kernel(const float* __restrict__ b3, const float* __restrict__ b4,
                 float* __restrict__ out, int N, int ntiles)
{
    extern __shared__ unsigned char smx[];
    const uint32_t sb = smem_u32(smx);
    const int t = threadIdx.x, w = t >> 5, lane = t & 31;
    const int g = lane >> 2, tid4 = lane & 3;

    // one-time stage: B3/B4 fragments (32KB) + biases
    {
        const uint4* gi = (const uint4*)(g_Bimg + 49152);
        uint4* s = (uint4*)smx;
        for (int i = t; i < 2048; i += 256) s[i] = gi[i];
        float* sbias = (float*)(smx + NOFF_BIAS);
        if (t < Dc) sbias[t] = b3[t];
        else if (t < 2 * Dc) sbias[t] = b4[t - Dc];
    }
    __syncthreads();

    const float* sb3 = (const float*)(smx + NOFF_BIAS);
    const float* sb4 = sb3 + Dc;
    const uint32_t aHbase = sb + NOFF_AHI + w * 2048;
    const uint32_t aLbase = sb + NOFF_ALO + w * 2048;

    for (int tile = blockIdx.x; tile < ntiles; tile += gridDim.x) {
        const int n0r = tile * TILE_E + w * 16;   // warp's first node row

        const int nr0 = min(n0r + g,     N - 1);
        const int nr1 = min(n0r + g + 8, N - 1);
        const bool v0 = (n0r + g)     < N;
        const bool v1 = (n0r + g + 8) < N;
        const float* p0 = g_s + (size_t)nr0 * Dc;
        const float* p1 = g_s + (size_t)nr1 * Dc;
        float c0 = g_cnt[nr0], c1 = g_cnt[nr1];
        const float inv0 = (c0 > 0.0f) ? (1.0f / c0) : 0.0f;
        const float inv1 = (c1 > 0.0f) ? (1.0f / c1) : 0.0f;

        float acc[8][4];
#pragma unroll
        for (int nt = 0; nt < 8; ++nt)
#pragma unroll
            for (int q = 0; q < 4; ++q) acc[nt][q] = 0.f;

        // ---- GEMM3: h1raw = agg @ W3, K=64 (4 k-steps) ----
#pragma unroll
        for (int ks = 0; ks < 4; ++ks) {
            const int k0 = ks * 16 + tid4 * 2;
            float2 x00 = *(const float2*)(p0 + k0);
            float2 x10 = *(const float2*)(p1 + k0);
            float2 x01 = *(const float2*)(p0 + k0 + 8);
            float2 x11 = *(const float2*)(p1 + k0 + 8);
            uint32_t aH[4], aL[4];
            split2(x00.x * inv0, x00.y * inv0, aH[0], aL[0]);
            split2(x10.x * inv1, x10.y * inv1, aH[1], aL[1]);
            split2(x01.x * inv0, x01.y * inv0, aH[2], aL[2]);
            split2(x11.x * inv1, x11.y * inv1, aH[3], aL[3]);
            const uint4* Bp = (const uint4*)(smx + NOFF_B3) + (ks * 8) * 32 + lane;
#pragma unroll
            for (int nt = 0; nt < 8; ++nt) {
                uint4 bb = Bp[nt * 32];
                mma16816(acc[nt], aH, bb.x, bb.y);
                mma16816(acc[nt], aH, bb.z, bb.w);
                mma16816(acc[nt], aL, bb.x, bb.y);
            }
        }

        // ---- bias + ssp + hi/lo split -> per-warp strips (swizzled) ----
#pragma unroll
        for (int nt = 0; nt < 8; ++nt) {
            int n = nt * 8 + tid4 * 2;
            float f0 = ssp_f(acc[nt][0] + sb3[n]);
            float f1 = ssp_f(acc[nt][1] + sb3[n + 1]);
            float f2 = ssp_f(acc[nt][2] + sb3[n]);
            float f3 = ssp_f(acc[nt][3] + sb3[n + 1]);
            uint32_t h01, l01, h23, l23;
            split2(f0, f1, h01, l01);
            split2(f2, f3, h23, l23);
            uint32_t o0 = swz((uint32_t)g       * 128 + (uint32_t)n * 2);
            uint32_t o1 = swz((uint32_t)(g + 8) * 128 + (uint32_t)n * 2);
            asm volatile("st.shared.b32 [%0], %1;" :: "r"(aHbase + o0), "r"(h01) : "memory");
            asm volatile("st.shared.b32 [%0], %1;" :: "r"(aHbase + o1), "r"(h23) : "memory");
            asm volatile("st.shared.b32 [%0], %1;" :: "r"(aLbase + o0), "r"(l01) : "memory");
            asm volatile("st.shared.b32 [%0], %1;" :: "r"(aLbase + o1), "r"(l23) : "memory");
#pragma unroll
            for (int q = 0; q < 4; ++q) acc[nt][q] = 0.f;
        }
        __syncwarp();

        // ---- GEMM4: outraw = h1 @ W4, K=64 (4 k-steps) ----
        {
            const int lrow = lane & 15, half = lane >> 4;
#pragma unroll
            for (int ks = 0; ks < 4; ++ks) {
                uint32_t off = swz((uint32_t)lrow * 128 + (uint32_t)ks * 32 + (uint32_t)half * 16);
                uint32_t aH[4], aL[4];
                ldmx4(aH, aHbase + off);
                ldmx4(aL, aLbase + off);
                const uint4* Bp = (const uint4*)(smx + NOFF_B4) + (ks * 8) * 32 + lane;
#pragma unroll
                for (int nt = 0; nt < 8; ++nt) {
                    uint4 bb = Bp[nt * 32];
                    mma16816(acc[nt], aH, bb.x, bb.y);
                    mma16816(acc[nt], aH, bb.z, bb.w);
                    mma16816(acc[nt], aL, bb.x, bb.y);
                }
            }
        }
        __syncwarp();   // strip reads complete before next tile overwrites

        // ---- epilogue: out = ssp(acc + b4), float2 stores ----
#pragma unroll
        for (int nt = 0; nt < 8; ++nt) {
            int n = nt * 8 + tid4 * 2;
            if (v0) {
                float2 o;
                o.x = ssp_f(acc[nt][0] + sb4[n]);
                o.y = ssp_f(acc[nt][1] + sb4[n + 1]);
                *(float2*)&out[(size_t)(n0r + g) * Dc + n] = o;
            }
            if (v1) {
                float2 o;
                o.x = ssp_f(acc[nt][2] + sb4[n]);
                o.y = ssp_f(acc[nt][3] + sb4[n + 1]);
                *(float2*)&out[(size_t)(n0r + g + 8) * Dc + n] = o;
            }
        }
    }
}

// ---------------------------------------------------------------------------
extern "C" void kernel_launch(void* const* d_in, const int* in_sizes, int n_in,
                              void* d_out, int out_size)
{
    const float* bf  = (const float*)d_in[0];
    const float* eh  = (const float*)d_in[1];
    const float* nh  = (const float*)d_in[2];
    const int*   src = (const int*)  d_in[3];
    const int*   dst = (const int*)  d_in[4];
    const float* W1  = (const float*)d_in[5];
    const float* b1  = (const float*)d_in[6];
    const float* W2  = (const float*)d_in[7];
    const float* b2  = (const float*)d_in[8];
    const float* W3  = (const float*)d_in[9];
    const float* b3  = (const float*)d_in[10];
    const float* W4  = (const float*)d_in[11];
    const float* b4  = (const float*)d_in[12];

    int E = in_sizes[3];
    int N = in_sizes[2] / Dc;

    cudaFuncSetAttribute(edge_kernel, cudaFuncAttributeMaxDynamicSharedMemorySize, SMEM_EDGE);
    cudaFuncSetAttribute(node_kernel, cudaFuncAttributeMaxDynamicSharedMemorySize, SMEM_NODE);

    int zero_grid = (N * (Dc / 4) + 255) / 256;
    zero_kernel<<<zero_grid, 256>>>(N);

    prep_kernel<<<8, 256>>>(W1, W2, W3, W4);

    int ntiles = (E + TILE_E - 1) / TILE_E;
    int egrid = ntiles < EDGE_GRID ? ntiles : EDGE_GRID;
    edge_kernel<<<egrid, 256, SMEM_EDGE>>>(bf, eh, nh, src, dst, b1, b2, E, ntiles);

    int ntiles_n = (N + TILE_E - 1) / TILE_E;
    int ngrid = ntiles_n < EDGE_GRID ? ntiles_n : EDGE_GRID;
    node_kernel<<<ngrid, 256, SMEM_NODE>>>(b3, b4, (float*)d_out, N, ntiles_n);
}

// round 14
// speedup vs baseline: 1.3688x; 1.2182x over previous
#include <cuda_runtime.h>
#include <cuda_bf16.h>
#include <cstdint>
#include <math.h>

// ---------------------------------------------------------------------------
// SchnetConv — R13 (persistent mma edge + node kernels, bf16 hi/lo 3-term)
// with fast ssp: log1pf -> __logf(1+e)  (e in (0,1], abs err ~1.6e-7).
// ---------------------------------------------------------------------------

#define Dc       64
#define Rc       128
#define TILE_E   128
#define N_MAX    100000
#define EDGE_GRID 296      // 2 CTAs/SM x 148 SMs

__device__ float g_s[(size_t)N_MAX * Dc];
__device__ float g_cnt[N_MAX];
// fragment-ordered weight image (uint4{hix,hiy,lox,loy} per (ks,nt,lane)):
// B1 [8ks][8nt][32] = 32KB | B2 [4ks][8nt][32] = 16KB | B3 = 16KB | B4 = 16KB
__device__ __align__(16) unsigned char g_Bimg[81920];

// edge SMEM layout (bytes)
#define OFF_B1    0
#define OFF_B2    32768
#define OFF_A2HI  49152     // 8 warps x 2048B (16 rows x 128B, swizzled)
#define OFF_A2LO  65536
#define OFF_BIAS  81920     // b1[64], b2[64]
#define SMEM_EDGE 82432

// node SMEM layout (bytes)
#define NOFF_B3    0
#define NOFF_B4    16384
#define NOFF_AHI   32768    // 8 warps x 2048B
#define NOFF_ALO   49152
#define NOFF_BIAS  65536    // b3[64], b4[64]
#define SMEM_NODE  66048

// ---- helpers ---------------------------------------------------------------
__device__ __forceinline__ float ssp_f(float x) {
    float e = __expf(-fabsf(x));
    return fmaxf(x, 0.0f) + __logf(1.0f + e) - 0.69314718055994531f;
}
__device__ __forceinline__ uint32_t swz(uint32_t off) { return off ^ ((off >> 3) & 0x70); }

__device__ __forceinline__ uint32_t smem_u32(const void* p) {
    uint32_t a;
    asm("{ .reg .u64 t; cvta.to.shared.u64 t, %1; cvt.u32.u64 %0, t; }" : "=r"(a) : "l"(p));
    return a;
}
// x = hi + lo (bf16 each); packs (x0 -> low half, x1 -> high half)
__device__ __forceinline__ void split2(float x0, float x1, uint32_t& hi, uint32_t& lo) {
    asm("cvt.rn.bf16x2.f32 %0, %1, %2;" : "=r"(hi) : "f"(x1), "f"(x0));
    float h0 = __uint_as_float(hi << 16);
    float h1 = __uint_as_float(hi & 0xffff0000u);
    asm("cvt.rn.bf16x2.f32 %0, %1, %2;" : "=r"(lo) : "f"(x1 - h1), "f"(x0 - h0));
}
__device__ __forceinline__ void mma16816(float* c, const uint32_t* a, uint32_t b0, uint32_t b1) {
    asm volatile(
        "mma.sync.aligned.m16n8k16.row.col.f32.bf16.bf16.f32 "
        "{%0,%1,%2,%3}, {%4,%5,%6,%7}, {%8,%9}, {%0,%1,%2,%3};"
        : "+f"(c[0]), "+f"(c[1]), "+f"(c[2]), "+f"(c[3])
        : "r"(a[0]), "r"(a[1]), "r"(a[2]), "r"(a[3]), "r"(b0), "r"(b1));
}
__device__ __forceinline__ void ldmx4(uint32_t* r, uint32_t addr) {
    asm volatile("ldmatrix.sync.aligned.m8n8.x4.shared.b16 {%0,%1,%2,%3}, [%4];"
        : "=r"(r[0]), "=r"(r[1]), "=r"(r[2]), "=r"(r[3]) : "r"(addr));
}

// ---------------------------------------------------------------------------
__global__ void zero_kernel(int n_nodes) {
    int i = blockIdx.x * 256 + threadIdx.x;
    int t4 = n_nodes * (Dc / 4);
    if (i < t4) ((float4*)g_s)[i] = make_float4(0.f, 0.f, 0.f, 0.f);
    if (i < n_nodes) g_cnt[i] = 0.0f;
}

// Build fragment-ordered hi/lo weight images for W1/W2/W3/W4.
__global__ void prep_kernel(const float* __restrict__ W1, const float* __restrict__ W2,
                            const float* __restrict__ W3, const float* __restrict__ W4) {
    int i = blockIdx.x * 256 + threadIdx.x;
    if (i < 2048) {   // B1: idx = (ks*8+nt)*32+lane
        int lane = i & 31, nt = (i >> 5) & 7, ks = i >> 8;
        int tid4 = lane & 3, g = lane >> 2;
        int k0 = ks * 16 + tid4 * 2;
        int n  = nt * 8 + g;
        float e00 = W1[(k0    ) * Dc + n], e01 = W1[(k0 + 1) * Dc + n];
        float e10 = W1[(k0 + 8) * Dc + n], e11 = W1[(k0 + 9) * Dc + n];
        uint32_t hx, lx, hy, ly;
        split2(e00, e01, hx, lx);
        split2(e10, e11, hy, ly);
        uint4 v; v.x = hx; v.y = hy; v.z = lx; v.w = ly;
        ((uint4*)g_Bimg)[i] = v;
    }
    if (i < 1024) {   // B2 / B3 / B4 (all 64x64)
        int lane = i & 31, nt = (i >> 5) & 7, ks = i >> 8;
        int tid4 = lane & 3, g = lane >> 2;
        int k0 = ks * 16 + tid4 * 2;
        int n  = nt * 8 + g;
        const float* Ws[3] = {W2, W3, W4};
        unsigned char* dsts[3] = {g_Bimg + 32768, g_Bimg + 49152, g_Bimg + 65536};
#pragma unroll
        for (int m = 0; m < 3; ++m) {
            const float* W = Ws[m];
            float e00 = W[(k0    ) * Dc + n], e01 = W[(k0 + 1) * Dc + n];
            float e10 = W[(k0 + 8) * Dc + n], e11 = W[(k0 + 9) * Dc + n];
            uint32_t hx, lx, hy, ly;
            split2(e00, e01, hx, lx);
            split2(e10, e11, hy, ly);
            uint4 v; v.x = hx; v.y = hy; v.z = lx; v.w = ly;
            ((uint4*)dsts[m])[i] = v;
        }
    }
}

// ---------------------------------------------------------------------------
// Persistent edge kernel: weights staged once, sync-free warp-local loop
// over 128-edge tiles (8 warps x 16 rows each).
// ---------------------------------------------------------------------------
__global__ __launch_bounds__(256, 2)
void edge_kernel(const float* __restrict__ bf, const float* __restrict__ eh,
                 const float* __restrict__ nh, const int* __restrict__ src,
                 const int* __restrict__ dst,
                 const float* __restrict__ b1, const float* __restrict__ b2,
                 int E, int ntiles)
{
    extern __shared__ unsigned char smx[];
    const uint32_t sb = smem_u32(smx);
    const int t = threadIdx.x, w = t >> 5, lane = t & 31;
    const int g = lane >> 2, tid4 = lane & 3;

    // one-time stage: weight fragments (48KB) + biases
    {
        const uint4* gi = (const uint4*)g_Bimg;
        uint4* s = (uint4*)smx;
        for (int i = t; i < 3072; i += 256) s[i] = gi[i];
        float* sbias = (float*)(smx + OFF_BIAS);
        if (t < Dc) sbias[t] = b1[t];
        else if (t < 2 * Dc) sbias[t] = b2[t - Dc];
    }
    __syncthreads();

    const float* sb1 = (const float*)(smx + OFF_BIAS);
    const float* sb2 = sb1 + Dc;
    const uint32_t aHbase = sb + OFF_A2HI + w * 2048;
    const uint32_t aLbase = sb + OFF_A2LO + w * 2048;

    for (int tile = blockIdx.x; tile < ntiles; tile += gridDim.x) {
        const int e0 = tile * TILE_E + w * 16;   // warp's first edge row

        const int er0 = min(e0 + g,     E - 1);
        const int er1 = min(e0 + g + 8, E - 1);
        const bool v0 = (e0 + g)     < E;
        const bool v1 = (e0 + g + 8) < E;
        const float* p0 = bf + (size_t)er0 * Rc;
        const float* p1 = bf + (size_t)er1 * Rc;

        float acc[8][4];
#pragma unroll
        for (int nt = 0; nt < 8; ++nt)
#pragma unroll
            for (int q = 0; q < 4; ++q) acc[nt][q] = 0.f;

        // ---- GEMM1: f1raw = bf @ W1, K=128 (8 k-steps), N=64 (8 n-tiles) ----
#pragma unroll
        for (int ks = 0; ks < 8; ++ks) {
            const int k0 = ks * 16 + tid4 * 2;
            float2 x00 = *(const float2*)(p0 + k0);
            float2 x10 = *(const float2*)(p1 + k0);
            float2 x01 = *(const float2*)(p0 + k0 + 8);
            float2 x11 = *(const float2*)(p1 + k0 + 8);
            uint32_t aH[4], aL[4];
            split2(x00.x, x00.y, aH[0], aL[0]);
            split2(x10.x, x10.y, aH[1], aL[1]);
            split2(x01.x, x01.y, aH[2], aL[2]);
            split2(x11.x, x11.y, aH[3], aL[3]);
            const uint4* Bp = (const uint4*)(smx + OFF_B1) + (ks * 8) * 32 + lane;
#pragma unroll
            for (int nt = 0; nt < 8; ++nt) {
                uint4 bb = Bp[nt * 32];
                mma16816(acc[nt], aH, bb.x, bb.y);   // Ah*Bh
                mma16816(acc[nt], aH, bb.z, bb.w);   // Ah*Bl
                mma16816(acc[nt], aL, bb.x, bb.y);   // Al*Bh
            }
        }

        // ---- bias + ssp + hi/lo split -> per-warp A2 strips (swizzled) ----
#pragma unroll
        for (int nt = 0; nt < 8; ++nt) {
            int n = nt * 8 + tid4 * 2;
            float f0 = ssp_f(acc[nt][0] + sb1[n]);
            float f1 = ssp_f(acc[nt][1] + sb1[n + 1]);
            float f2 = ssp_f(acc[nt][2] + sb1[n]);
            float f3 = ssp_f(acc[nt][3] + sb1[n + 1]);
            uint32_t h01, l01, h23, l23;
            split2(f0, f1, h01, l01);
            split2(f2, f3, h23, l23);
            uint32_t o0 = swz((uint32_t)g       * 128 + (uint32_t)n * 2);
            uint32_t o1 = swz((uint32_t)(g + 8) * 128 + (uint32_t)n * 2);
            asm volatile("st.shared.b32 [%0], %1;" :: "r"(aHbase + o0), "r"(h01) : "memory");
            asm volatile("st.shared.b32 [%0], %1;" :: "r"(aHbase + o1), "r"(h23) : "memory");
            asm volatile("st.shared.b32 [%0], %1;" :: "r"(aLbase + o0), "r"(l01) : "memory");
            asm volatile("st.shared.b32 [%0], %1;" :: "r"(aLbase + o1), "r"(l23) : "memory");
#pragma unroll
            for (int q = 0; q < 4; ++q) acc[nt][q] = 0.f;
        }
        __syncwarp();

        // ---- GEMM2: f2raw = f1 @ W2, K=64 (4 k-steps) ----
        {
            const int lrow = lane & 15, half = lane >> 4;
#pragma unroll
            for (int ks = 0; ks < 4; ++ks) {
                uint32_t off = swz((uint32_t)lrow * 128 + (uint32_t)ks * 32 + (uint32_t)half * 16);
                uint32_t aH[4], aL[4];
                ldmx4(aH, aHbase + off);
                ldmx4(aL, aLbase + off);
                const uint4* Bp = (const uint4*)(smx + OFF_B2) + (ks * 8) * 32 + lane;
#pragma unroll
                for (int nt = 0; nt < 8; ++nt) {
                    uint4 bb = Bp[nt * 32];
                    mma16816(acc[nt], aH, bb.x, bb.y);
                    mma16816(acc[nt], aH, bb.z, bb.w);
                    mma16816(acc[nt], aL, bb.x, bb.y);
                }
            }
        }
        __syncwarp();   // A2 strip reads complete before next tile overwrites

        // ---- epilogue: m = f2 * eh * nh[src]; red.global.v2 to g_s ----
        int sv0 = 0, dv0 = 0, sv1 = 0, dv1 = 0;
        if (v0) { sv0 = src[e0 + g];     dv0 = dst[e0 + g]; }
        if (v1) { sv1 = src[e0 + g + 8]; dv1 = dst[e0 + g + 8]; }
        if (tid4 == 0) {
            if (v0) atomicAdd(&g_cnt[dv0], 1.0f);
            if (v1) atomicAdd(&g_cnt[dv1], 1.0f);
        }
#pragma unroll
        for (int nt = 0; nt < 8; ++nt) {
            int n = nt * 8 + tid4 * 2;
            if (v0) {
                float f0 = ssp_f(acc[nt][0] + sb2[n]);
                float f1 = ssp_f(acc[nt][1] + sb2[n + 1]);
                float2 ev = *(const float2*)&eh[(size_t)(e0 + g) * Dc + n];
                float2 nv = *(const float2*)&nh[(size_t)sv0 * Dc + n];
                float m0 = f0 * ev.x * nv.x;
                float m1 = f1 * ev.y * nv.y;
                float* gp = &g_s[(size_t)dv0 * Dc + n];
                asm volatile("red.global.add.v2.f32 [%0], {%1, %2};"
                             :: "l"(gp), "f"(m0), "f"(m1) : "memory");
            }
            if (v1) {
                float f2 = ssp_f(acc[nt][2] + sb2[n]);
                float f3 = ssp_f(acc[nt][3] + sb2[n + 1]);
                float2 ev = *(const float2*)&eh[(size_t)(e0 + g + 8) * Dc + n];
                float2 nv = *(const float2*)&nh[(size_t)sv1 * Dc + n];
                float m2 = f2 * ev.x * nv.x;
                float m3 = f3 * ev.y * nv.y;
                float* gp = &g_s[(size_t)dv1 * Dc + n];
                asm volatile("red.global.add.v2.f32 [%0], {%1, %2};"
                             :: "l"(gp), "f"(m2), "f"(m3) : "memory");
            }
        }
    }
}

// ---------------------------------------------------------------------------
// Persistent mma node kernel: agg = g_s*inv_cnt -> MLP3 -> MLP4 -> out.
// ---------------------------------------------------------------------------
__global__ __launch_bounds__(256, 2)
void node_kernel(const float* __restrict__ b3, const float* __restrict__ b4,
                 float* __restrict__ out, int N, int ntiles)
{
    extern __shared__ unsigned char smx[];
    const uint32_t sb = smem_u32(smx);
    const int t = threadIdx.x, w = t >> 5, lane = t & 31;
    const int g = lane >> 2, tid4 = lane & 3;

    // one-time stage: B3/B4 fragments (32KB) + biases
    {
        const uint4* gi = (const uint4*)(g_Bimg + 49152);
        uint4* s = (uint4*)smx;
        for (int i = t; i < 2048; i += 256) s[i] = gi[i];
        float* sbias = (float*)(smx + NOFF_BIAS);
        if (t < Dc) sbias[t] = b3[t];
        else if (t < 2 * Dc) sbias[t] = b4[t - Dc];
    }
    __syncthreads();

    const float* sb3 = (const float*)(smx + NOFF_BIAS);
    const float* sb4 = sb3 + Dc;
    const uint32_t aHbase = sb + NOFF_AHI + w * 2048;
    const uint32_t aLbase = sb + NOFF_ALO + w * 2048;

    for (int tile = blockIdx.x; tile < ntiles; tile += gridDim.x) {
        const int n0r = tile * TILE_E + w * 16;   // warp's first node row

        const int nr0 = min(n0r + g,     N - 1);
        const int nr1 = min(n0r + g + 8, N - 1);
        const bool v0 = (n0r + g)     < N;
        const bool v1 = (n0r + g + 8) < N;
        const float* p0 = g_s + (size_t)nr0 * Dc;
        const float* p1 = g_s + (size_t)nr1 * Dc;
        float c0 = g_cnt[nr0], c1 = g_cnt[nr1];
        const float inv0 = (c0 > 0.0f) ? (1.0f / c0) : 0.0f;
        const float inv1 = (c1 > 0.0f) ? (1.0f / c1) : 0.0f;

        float acc[8][4];
#pragma unroll
        for (int nt = 0; nt < 8; ++nt)
#pragma unroll
            for (int q = 0; q < 4; ++q) acc[nt][q] = 0.f;

        // ---- GEMM3: h1raw = agg @ W3, K=64 (4 k-steps) ----
#pragma unroll
        for (int ks = 0; ks < 4; ++ks) {
            const int k0 = ks * 16 + tid4 * 2;
            float2 x00 = *(const float2*)(p0 + k0);
            float2 x10 = *(const float2*)(p1 + k0);
            float2 x01 = *(const float2*)(p0 + k0 + 8);
            float2 x11 = *(const float2*)(p1 + k0 + 8);
            uint32_t aH[4], aL[4];
            split2(x00.x * inv0, x00.y * inv0, aH[0], aL[0]);
            split2(x10.x * inv1, x10.y * inv1, aH[1], aL[1]);
            split2(x01.x * inv0, x01.y * inv0, aH[2], aL[2]);
            split2(x11.x * inv1, x11.y * inv1, aH[3], aL[3]);
            const uint4* Bp = (const uint4*)(smx + NOFF_B3) + (ks * 8) * 32 + lane;
#pragma unroll
            for (int nt = 0; nt < 8; ++nt) {
                uint4 bb = Bp[nt * 32];
                mma16816(acc[nt], aH, bb.x, bb.y);
                mma16816(acc[nt], aH, bb.z, bb.w);
                mma16816(acc[nt], aL, bb.x, bb.y);
            }
        }

        // ---- bias + ssp + hi/lo split -> per-warp strips (swizzled) ----
#pragma unroll
        for (int nt = 0; nt < 8; ++nt) {
            int n = nt * 8 + tid4 * 2;
            float f0 = ssp_f(acc[nt][0] + sb3[n]);
            float f1 = ssp_f(acc[nt][1] + sb3[n + 1]);
            float f2 = ssp_f(acc[nt][2] + sb3[n]);
            float f3 = ssp_f(acc[nt][3] + sb3[n + 1]);
            uint32_t h01, l01, h23, l23;
            split2(f0, f1, h01, l01);
            split2(f2, f3, h23, l23);
            uint32_t o0 = swz((uint32_t)g       * 128 + (uint32_t)n * 2);
            uint32_t o1 = swz((uint32_t)(g + 8) * 128 + (uint32_t)n * 2);
            asm volatile("st.shared.b32 [%0], %1;" :: "r"(aHbase + o0), "r"(h01) : "memory");
            asm volatile("st.shared.b32 [%0], %1;" :: "r"(aHbase + o1), "r"(h23) : "memory");
            asm volatile("st.shared.b32 [%0], %1;" :: "r"(aLbase + o0), "r"(l01) : "memory");
            asm volatile("st.shared.b32 [%0], %1;" :: "r"(aLbase + o1), "r"(l23) : "memory");
#pragma unroll
            for (int q = 0; q < 4; ++q) acc[nt][q] = 0.f;
        }
        __syncwarp();

        // ---- GEMM4: outraw = h1 @ W4, K=64 (4 k-steps) ----
        {
            const int lrow = lane & 15, half = lane >> 4;
#pragma unroll
            for (int ks = 0; ks < 4; ++ks) {
                uint32_t off = swz((uint32_t)lrow * 128 + (uint32_t)ks * 32 + (uint32_t)half * 16);
                uint32_t aH[4], aL[4];
                ldmx4(aH, aHbase + off);
                ldmx4(aL, aLbase + off);
                const uint4* Bp = (const uint4*)(smx + NOFF_B4) + (ks * 8) * 32 + lane;
#pragma unroll
                for (int nt = 0; nt < 8; ++nt) {
                    uint4 bb = Bp[nt * 32];
                    mma16816(acc[nt], aH, bb.x, bb.y);
                    mma16816(acc[nt], aH, bb.z, bb.w);
                    mma16816(acc[nt], aL, bb.x, bb.y);
                }
            }
        }
        __syncwarp();   // strip reads complete before next tile overwrites

        // ---- epilogue: out = ssp(acc + b4), float2 stores ----
#pragma unroll
        for (int nt = 0; nt < 8; ++nt) {
            int n = nt * 8 + tid4 * 2;
            if (v0) {
                float2 o;
                o.x = ssp_f(acc[nt][0] + sb4[n]);
                o.y = ssp_f(acc[nt][1] + sb4[n + 1]);
                *(float2*)&out[(size_t)(n0r + g) * Dc + n] = o;
            }
            if (v1) {
                float2 o;
                o.x = ssp_f(acc[nt][2] + sb4[n]);
                o.y = ssp_f(acc[nt][3] + sb4[n + 1]);
                *(float2*)&out[(size_t)(n0r + g + 8) * Dc + n] = o;
            }
        }
    }
}

// ---------------------------------------------------------------------------
extern "C" void kernel_launch(void* const* d_in, const int* in_sizes, int n_in,
                              void* d_out, int out_size)
{
    const float* bf  = (const float*)d_in[0];
    const float* eh  = (const float*)d_in[1];
    const float* nh  = (const float*)d_in[2];
    const int*   src = (const int*)  d_in[3];
    const int*   dst = (const int*)  d_in[4];
    const float* W1  = (const float*)d_in[5];
    const float* b1  = (const float*)d_in[6];
    const float* W2  = (const float*)d_in[7];
    const float* b2  = (const float*)d_in[8];
    const float* W3  = (const float*)d_in[9];
    const float* b3  = (const float*)d_in[10];
    const float* W4  = (const float*)d_in[11];
    const float* b4  = (const float*)d_in[12];

    int E = in_sizes[3];
    int N = in_sizes[2] / Dc;

    cudaFuncSetAttribute(edge_kernel, cudaFuncAttributeMaxDynamicSharedMemorySize, SMEM_EDGE);
    cudaFuncSetAttribute(node_kernel, cudaFuncAttributeMaxDynamicSharedMemorySize, SMEM_NODE);

    int zero_grid = (N * (Dc / 4) + 255) / 256;
    zero_kernel<<<zero_grid, 256>>>(N);

    prep_kernel<<<8, 256>>>(W1, W2, W3, W4);

    int ntiles = (E + TILE_E - 1) / TILE_E;
    int egrid = ntiles < EDGE_GRID ? ntiles : EDGE_GRID;
    edge_kernel<<<egrid, 256, SMEM_EDGE>>>(bf, eh, nh, src, dst, b1, b2, E, ntiles);

    int ntiles_n = (N + TILE_E - 1) / TILE_E;
    int ngrid = ntiles_n < EDGE_GRID ? ntiles_n : EDGE_GRID;
    node_kernel<<<ngrid, 256, SMEM_NODE>>>(b3, b4, (float*)d_out, N, ntiles_n);
}

// round 15
// speedup vs baseline: 1.3699x; 1.0008x over previous
#include <cuda_runtime.h>
#include <cuda_bf16.h>
#include <cstdint>
#include <math.h>

// ---------------------------------------------------------------------------
// SchnetConv — R14 (persistent mma edge+node, bf16 hi/lo 3-term, fast ssp)
// with PER-WARP independent work streams: each warp grid-strides over its
// own 16-row blocks, de-phasing tensor/LSU phases across warps.
// ---------------------------------------------------------------------------

#define Dc       64
#define Rc       128
#define N_MAX    100000
#define EDGE_GRID 296      // 2 CTAs/SM x 148 SMs

__device__ float g_s[(size_t)N_MAX * Dc];
__device__ float g_cnt[N_MAX];
// fragment-ordered weight image (uint4{hix,hiy,lox,loy} per (ks,nt,lane)):
// B1 [8ks][8nt][32] = 32KB | B2 [4ks][8nt][32] = 16KB | B3 = 16KB | B4 = 16KB
__device__ __align__(16) unsigned char g_Bimg[81920];

// edge SMEM layout (bytes)
#define OFF_B1    0
#define OFF_B2    32768
#define OFF_A2HI  49152     // 8 warps x 2048B (16 rows x 128B, swizzled)
#define OFF_A2LO  65536
#define OFF_BIAS  81920     // b1[64], b2[64]
#define SMEM_EDGE 82432

// node SMEM layout (bytes)
#define NOFF_B3    0
#define NOFF_B4    16384
#define NOFF_AHI   32768    // 8 warps x 2048B
#define NOFF_ALO   49152
#define NOFF_BIAS  65536    // b3[64], b4[64]
#define SMEM_NODE  66048

// ---- helpers ---------------------------------------------------------------
__device__ __forceinline__ float ssp_f(float x) {
    float e = __expf(-fabsf(x));
    return fmaxf(x, 0.0f) + __logf(1.0f + e) - 0.69314718055994531f;
}
__device__ __forceinline__ uint32_t swz(uint32_t off) { return off ^ ((off >> 3) & 0x70); }

__device__ __forceinline__ uint32_t smem_u32(const void* p) {
    uint32_t a;
    asm("{ .reg .u64 t; cvta.to.shared.u64 t, %1; cvt.u32.u64 %0, t; }" : "=r"(a) : "l"(p));
    return a;
}
// x = hi + lo (bf16 each); packs (x0 -> low half, x1 -> high half)
__device__ __forceinline__ void split2(float x0, float x1, uint32_t& hi, uint32_t& lo) {
    asm("cvt.rn.bf16x2.f32 %0, %1, %2;" : "=r"(hi) : "f"(x1), "f"(x0));
    float h0 = __uint_as_float(hi << 16);
    float h1 = __uint_as_float(hi & 0xffff0000u);
    asm("cvt.rn.bf16x2.f32 %0, %1, %2;" : "=r"(lo) : "f"(x1 - h1), "f"(x0 - h0));
}
__device__ __forceinline__ void mma16816(float* c, const uint32_t* a, uint32_t b0, uint32_t b1) {
    asm volatile(
        "mma.sync.aligned.m16n8k16.row.col.f32.bf16.bf16.f32 "
        "{%0,%1,%2,%3}, {%4,%5,%6,%7}, {%8,%9}, {%0,%1,%2,%3};"
        : "+f"(c[0]), "+f"(c[1]), "+f"(c[2]), "+f"(c[3])
        : "r"(a[0]), "r"(a[1]), "r"(a[2]), "r"(a[3]), "r"(b0), "r"(b1));
}
__device__ __forceinline__ void ldmx4(uint32_t* r, uint32_t addr) {
    asm volatile("ldmatrix.sync.aligned.m8n8.x4.shared.b16 {%0,%1,%2,%3}, [%4];"
        : "=r"(r[0]), "=r"(r[1]), "=r"(r[2]), "=r"(r[3]) : "r"(addr));
}

// ---------------------------------------------------------------------------
__global__ void zero_kernel(int n_nodes) {
    int i = blockIdx.x * 256 + threadIdx.x;
    int t4 = n_nodes * (Dc / 4);
    if (i < t4) ((float4*)g_s)[i] = make_float4(0.f, 0.f, 0.f, 0.f);
    if (i < n_nodes) g_cnt[i] = 0.0f;
}

// Build fragment-ordered hi/lo weight images for W1/W2/W3/W4.
__global__ void prep_kernel(const float* __restrict__ W1, const float* __restrict__ W2,
                            const float* __restrict__ W3, const float* __restrict__ W4) {
    int i = blockIdx.x * 256 + threadIdx.x;
    if (i < 2048) {   // B1: idx = (ks*8+nt)*32+lane
        int lane = i & 31, nt = (i >> 5) & 7, ks = i >> 8;
        int tid4 = lane & 3, g = lane >> 2;
        int k0 = ks * 16 + tid4 * 2;
        int n  = nt * 8 + g;
        float e00 = W1[(k0    ) * Dc + n], e01 = W1[(k0 + 1) * Dc + n];
        float e10 = W1[(k0 + 8) * Dc + n], e11 = W1[(k0 + 9) * Dc + n];
        uint32_t hx, lx, hy, ly;
        split2(e00, e01, hx, lx);
        split2(e10, e11, hy, ly);
        uint4 v; v.x = hx; v.y = hy; v.z = lx; v.w = ly;
        ((uint4*)g_Bimg)[i] = v;
    }
    if (i < 1024) {   // B2 / B3 / B4 (all 64x64)
        int lane = i & 31, nt = (i >> 5) & 7, ks = i >> 8;
        int tid4 = lane & 3, g = lane >> 2;
        int k0 = ks * 16 + tid4 * 2;
        int n  = nt * 8 + g;
        const float* Ws[3] = {W2, W3, W4};
        unsigned char* dsts[3] = {g_Bimg + 32768, g_Bimg + 49152, g_Bimg + 65536};
#pragma unroll
        for (int m = 0; m < 3; ++m) {
            const float* W = Ws[m];
            float e00 = W[(k0    ) * Dc + n], e01 = W[(k0 + 1) * Dc + n];
            float e10 = W[(k0 + 8) * Dc + n], e11 = W[(k0 + 9) * Dc + n];
            uint32_t hx, lx, hy, ly;
            split2(e00, e01, hx, lx);
            split2(e10, e11, hy, ly);
            uint4 v; v.x = hx; v.y = hy; v.z = lx; v.w = ly;
            ((uint4*)dsts[m])[i] = v;
        }
    }
}

// ---------------------------------------------------------------------------
// Persistent edge kernel: weights staged once, then each WARP independently
// grid-strides over 16-edge blocks (fully warp-local pipeline).
// ---------------------------------------------------------------------------
__global__ __launch_bounds__(256, 2)
void edge_kernel(const float* __restrict__ bf, const float* __restrict__ eh,
                 const float* __restrict__ nh, const int* __restrict__ src,
                 const int* __restrict__ dst,
                 const float* __restrict__ b1, const float* __restrict__ b2,
                 int E, int nblk)
{
    extern __shared__ unsigned char smx[];
    const uint32_t sb = smem_u32(smx);
    const int t = threadIdx.x, w = t >> 5, lane = t & 31;
    const int g = lane >> 2, tid4 = lane & 3;

    // one-time stage: weight fragments (48KB) + biases
    {
        const uint4* gi = (const uint4*)g_Bimg;
        uint4* s = (uint4*)smx;
        for (int i = t; i < 3072; i += 256) s[i] = gi[i];
        float* sbias = (float*)(smx + OFF_BIAS);
        if (t < Dc) sbias[t] = b1[t];
        else if (t < 2 * Dc) sbias[t] = b2[t - Dc];
    }
    __syncthreads();

    const float* sb1 = (const float*)(smx + OFF_BIAS);
    const float* sb2 = sb1 + Dc;
    const uint32_t aHbase = sb + OFF_A2HI + w * 2048;
    const uint32_t aLbase = sb + OFF_A2LO + w * 2048;

    const int gw = blockIdx.x * 8 + w;       // global warp-stream id
    const int nstreams = gridDim.x * 8;

    for (int blk = gw; blk < nblk; blk += nstreams) {
        const int e0 = blk * 16;             // this warp's 16-edge block

        const int er0 = min(e0 + g,     E - 1);
        const int er1 = min(e0 + g + 8, E - 1);
        const bool v0 = (e0 + g)     < E;
        const bool v1 = (e0 + g + 8) < E;
        const float* p0 = bf + (size_t)er0 * Rc;
        const float* p1 = bf + (size_t)er1 * Rc;

        float acc[8][4];
#pragma unroll
        for (int nt = 0; nt < 8; ++nt)
#pragma unroll
            for (int q = 0; q < 4; ++q) acc[nt][q] = 0.f;

        // ---- GEMM1: f1raw = bf @ W1, K=128 (8 k-steps), N=64 (8 n-tiles) ----
#pragma unroll
        for (int ks = 0; ks < 8; ++ks) {
            const int k0 = ks * 16 + tid4 * 2;
            float2 x00 = *(const float2*)(p0 + k0);
            float2 x10 = *(const float2*)(p1 + k0);
            float2 x01 = *(const float2*)(p0 + k0 + 8);
            float2 x11 = *(const float2*)(p1 + k0 + 8);
            uint32_t aH[4], aL[4];
            split2(x00.x, x00.y, aH[0], aL[0]);
            split2(x10.x, x10.y, aH[1], aL[1]);
            split2(x01.x, x01.y, aH[2], aL[2]);
            split2(x11.x, x11.y, aH[3], aL[3]);
            const uint4* Bp = (const uint4*)(smx + OFF_B1) + (ks * 8) * 32 + lane;
#pragma unroll
            for (int nt = 0; nt < 8; ++nt) {
                uint4 bb = Bp[nt * 32];
                mma16816(acc[nt], aH, bb.x, bb.y);   // Ah*Bh
                mma16816(acc[nt], aH, bb.z, bb.w);   // Ah*Bl
                mma16816(acc[nt], aL, bb.x, bb.y);   // Al*Bh
            }
        }

        // ---- bias + ssp + hi/lo split -> per-warp A2 strips (swizzled) ----
#pragma unroll
        for (int nt = 0; nt < 8; ++nt) {
            int n = nt * 8 + tid4 * 2;
            float f0 = ssp_f(acc[nt][0] + sb1[n]);
            float f1 = ssp_f(acc[nt][1] + sb1[n + 1]);
            float f2 = ssp_f(acc[nt][2] + sb1[n]);
            float f3 = ssp_f(acc[nt][3] + sb1[n + 1]);
            uint32_t h01, l01, h23, l23;
            split2(f0, f1, h01, l01);
            split2(f2, f3, h23, l23);
            uint32_t o0 = swz((uint32_t)g       * 128 + (uint32_t)n * 2);
            uint32_t o1 = swz((uint32_t)(g + 8) * 128 + (uint32_t)n * 2);
            asm volatile("st.shared.b32 [%0], %1;" :: "r"(aHbase + o0), "r"(h01) : "memory");
            asm volatile("st.shared.b32 [%0], %1;" :: "r"(aHbase + o1), "r"(h23) : "memory");
            asm volatile("st.shared.b32 [%0], %1;" :: "r"(aLbase + o0), "r"(l01) : "memory");
            asm volatile("st.shared.b32 [%0], %1;" :: "r"(aLbase + o1), "r"(l23) : "memory");
#pragma unroll
            for (int q = 0; q < 4; ++q) acc[nt][q] = 0.f;
        }
        __syncwarp();

        // ---- GEMM2: f2raw = f1 @ W2, K=64 (4 k-steps) ----
        {
            const int lrow = lane & 15, half = lane >> 4;
#pragma unroll
            for (int ks = 0; ks < 4; ++ks) {
                uint32_t off = swz((uint32_t)lrow * 128 + (uint32_t)ks * 32 + (uint32_t)half * 16);
                uint32_t aH[4], aL[4];
                ldmx4(aH, aHbase + off);
                ldmx4(aL, aLbase + off);
                const uint4* Bp = (const uint4*)(smx + OFF_B2) + (ks * 8) * 32 + lane;
#pragma unroll
                for (int nt = 0; nt < 8; ++nt) {
                    uint4 bb = Bp[nt * 32];
                    mma16816(acc[nt], aH, bb.x, bb.y);
                    mma16816(acc[nt], aH, bb.z, bb.w);
                    mma16816(acc[nt], aL, bb.x, bb.y);
                }
            }
        }
        __syncwarp();   // A2 strip reads complete before next block overwrites

        // ---- epilogue: m = f2 * eh * nh[src]; red.global.v2 to g_s ----
        int sv0 = 0, dv0 = 0, sv1 = 0, dv1 = 0;
        if (v0) { sv0 = src[e0 + g];     dv0 = dst[e0 + g]; }
        if (v1) { sv1 = src[e0 + g + 8]; dv1 = dst[e0 + g + 8]; }
        if (tid4 == 0) {
            if (v0) atomicAdd(&g_cnt[dv0], 1.0f);
            if (v1) atomicAdd(&g_cnt[dv1], 1.0f);
        }
#pragma unroll
        for (int nt = 0; nt < 8; ++nt) {
            int n = nt * 8 + tid4 * 2;
            if (v0) {
                float f0 = ssp_f(acc[nt][0] + sb2[n]);
                float f1 = ssp_f(acc[nt][1] + sb2[n + 1]);
                float2 ev = *(const float2*)&eh[(size_t)(e0 + g) * Dc + n];
                float2 nv = *(const float2*)&nh[(size_t)sv0 * Dc + n];
                float m0 = f0 * ev.x * nv.x;
                float m1 = f1 * ev.y * nv.y;
                float* gp = &g_s[(size_t)dv0 * Dc + n];
                asm volatile("red.global.add.v2.f32 [%0], {%1, %2};"
                             :: "l"(gp), "f"(m0), "f"(m1) : "memory");
            }
            if (v1) {
                float f2 = ssp_f(acc[nt][2] + sb2[n]);
                float f3 = ssp_f(acc[nt][3] + sb2[n + 1]);
                float2 ev = *(const float2*)&eh[(size_t)(e0 + g + 8) * Dc + n];
                float2 nv = *(const float2*)&nh[(size_t)sv1 * Dc + n];
                float m2 = f2 * ev.x * nv.x;
                float m3 = f3 * ev.y * nv.y;
                float* gp = &g_s[(size_t)dv1 * Dc + n];
                asm volatile("red.global.add.v2.f32 [%0], {%1, %2};"
                             :: "l"(gp), "f"(m2), "f"(m3) : "memory");
            }
        }
    }
}

// ---------------------------------------------------------------------------
// Persistent mma node kernel: agg = g_s*inv_cnt -> MLP3 -> MLP4 -> out.
// Per-warp 16-node streams.
// ---------------------------------------------------------------------------
__global__ __launch_bounds__(256, 2)
void node_kernel(const float* __restrict__ b3, const float* __restrict__ b4,
                 float* __restrict__ out, int N, int nblk)
{
    extern __shared__ unsigned char smx[];
    const uint32_t sb = smem_u32(smx);
    const int t = threadIdx.x, w = t >> 5, lane = t & 31;
    const int g = lane >> 2, tid4 = lane & 3;

    // one-time stage: B3/B4 fragments (32KB) + biases
    {
        const uint4* gi = (const uint4*)(g_Bimg + 49152);
        uint4* s = (uint4*)smx;
        for (int i = t; i < 2048; i += 256) s[i] = gi[i];
        float* sbias = (float*)(smx + NOFF_BIAS);
        if (t < Dc) sbias[t] = b3[t];
        else if (t < 2 * Dc) sbias[t] = b4[t - Dc];
    }
    __syncthreads();

    const float* sb3 = (const float*)(smx + NOFF_BIAS);
    const float* sb4 = sb3 + Dc;
    const uint32_t aHbase = sb + NOFF_AHI + w * 2048;
    const uint32_t aLbase = sb + NOFF_ALO + w * 2048;

    const int gw = blockIdx.x * 8 + w;
    const int nstreams = gridDim.x * 8;

    for (int blk = gw; blk < nblk; blk += nstreams) {
        const int n0r = blk * 16;

        const int nr0 = min(n0r + g,     N - 1);
        const int nr1 = min(n0r + g + 8, N - 1);
        const bool v0 = (n0r + g)     < N;
        const bool v1 = (n0r + g + 8) < N;
        const float* p0 = g_s + (size_t)nr0 * Dc;
        const float* p1 = g_s + (size_t)nr1 * Dc;
        float c0 = g_cnt[nr0], c1 = g_cnt[nr1];
        const float inv0 = (c0 > 0.0f) ? (1.0f / c0) : 0.0f;
        const float inv1 = (c1 > 0.0f) ? (1.0f / c1) : 0.0f;

        float acc[8][4];
#pragma unroll
        for (int nt = 0; nt < 8; ++nt)
#pragma unroll
            for (int q = 0; q < 4; ++q) acc[nt][q] = 0.f;

        // ---- GEMM3: h1raw = agg @ W3, K=64 (4 k-steps) ----
#pragma unroll
        for (int ks = 0; ks < 4; ++ks) {
            const int k0 = ks * 16 + tid4 * 2;
            float2 x00 = *(const float2*)(p0 + k0);
            float2 x10 = *(const float2*)(p1 + k0);
            float2 x01 = *(const float2*)(p0 + k0 + 8);
            float2 x11 = *(const float2*)(p1 + k0 + 8);
            uint32_t aH[4], aL[4];
            split2(x00.x * inv0, x00.y * inv0, aH[0], aL[0]);
            split2(x10.x * inv1, x10.y * inv1, aH[1], aL[1]);
            split2(x01.x * inv0, x01.y * inv0, aH[2], aL[2]);
            split2(x11.x * inv1, x11.y * inv1, aH[3], aL[3]);
            const uint4* Bp = (const uint4*)(smx + NOFF_B3) + (ks * 8) * 32 + lane;
#pragma unroll
            for (int nt = 0; nt < 8; ++nt) {
                uint4 bb = Bp[nt * 32];
                mma16816(acc[nt], aH, bb.x, bb.y);
                mma16816(acc[nt], aH, bb.z, bb.w);
                mma16816(acc[nt], aL, bb.x, bb.y);
            }
        }

        // ---- bias + ssp + hi/lo split -> per-warp strips (swizzled) ----
#pragma unroll
        for (int nt = 0; nt < 8; ++nt) {
            int n = nt * 8 + tid4 * 2;
            float f0 = ssp_f(acc[nt][0] + sb3[n]);
            float f1 = ssp_f(acc[nt][1] + sb3[n + 1]);
            float f2 = ssp_f(acc[nt][2] + sb3[n]);
            float f3 = ssp_f(acc[nt][3] + sb3[n + 1]);
            uint32_t h01, l01, h23, l23;
            split2(f0, f1, h01, l01);
            split2(f2, f3, h23, l23);
            uint32_t o0 = swz((uint32_t)g       * 128 + (uint32_t)n * 2);
            uint32_t o1 = swz((uint32_t)(g + 8) * 128 + (uint32_t)n * 2);
            asm volatile("st.shared.b32 [%0], %1;" :: "r"(aHbase + o0), "r"(h01) : "memory");
            asm volatile("st.shared.b32 [%0], %1;" :: "r"(aHbase + o1), "r"(h23) : "memory");
            asm volatile("st.shared.b32 [%0], %1;" :: "r"(aLbase + o0), "r"(l01) : "memory");
            asm volatile("st.shared.b32 [%0], %1;" :: "r"(aLbase + o1), "r"(l23) : "memory");
#pragma unroll
            for (int q = 0; q < 4; ++q) acc[nt][q] = 0.f;
        }
        __syncwarp();

        // ---- GEMM4: outraw = h1 @ W4, K=64 (4 k-steps) ----
        {
            const int lrow = lane & 15, half = lane >> 4;
#pragma unroll
            for (int ks = 0; ks < 4; ++ks) {
                uint32_t off = swz((uint32_t)lrow * 128 + (uint32_t)ks * 32 + (uint32_t)half * 16);
                uint32_t aH[4], aL[4];
                ldmx4(aH, aHbase + off);
                ldmx4(aL, aLbase + off);
                const uint4* Bp = (const uint4*)(smx + NOFF_B4) + (ks * 8) * 32 + lane;
#pragma unroll
                for (int nt = 0; nt < 8; ++nt) {
                    uint4 bb = Bp[nt * 32];
                    mma16816(acc[nt], aH, bb.x, bb.y);
                    mma16816(acc[nt], aH, bb.z, bb.w);
                    mma16816(acc[nt], aL, bb.x, bb.y);
                }
            }
        }
        __syncwarp();   // strip reads complete before next block overwrites

        // ---- epilogue: out = ssp(acc + b4), float2 stores ----
#pragma unroll
        for (int nt = 0; nt < 8; ++nt) {
            int n = nt * 8 + tid4 * 2;
            if (v0) {
                float2 o;
                o.x = ssp_f(acc[nt][0] + sb4[n]);
                o.y = ssp_f(acc[nt][1] + sb4[n + 1]);
                *(float2*)&out[(size_t)(n0r + g) * Dc + n] = o;
            }
            if (v1) {
                float2 o;
                o.x = ssp_f(acc[nt][2] + sb4[n]);
                o.y = ssp_f(acc[nt][3] + sb4[n + 1]);
                *(float2*)&out[(size_t)(n0r + g + 8) * Dc + n] = o;
            }
        }
    }
}

// ---------------------------------------------------------------------------
extern "C" void kernel_launch(void* const* d_in, const int* in_sizes, int n_in,
                              void* d_out, int out_size)
{
    const float* bf  = (const float*)d_in[0];
    const float* eh  = (const float*)d_in[1];
    const float* nh  = (const float*)d_in[2];
    const int*   src = (const int*)  d_in[3];
    const int*   dst = (const int*)  d_in[4];
    const float* W1  = (const float*)d_in[5];
    const float* b1  = (const float*)d_in[6];
    const float* W2  = (const float*)d_in[7];
    const float* b2  = (const float*)d_in[8];
    const float* W3  = (const float*)d_in[9];
    const float* b3  = (const float*)d_in[10];
    const float* W4  = (const float*)d_in[11];
    const float* b4  = (const float*)d_in[12];

    int E = in_sizes[3];
    int N = in_sizes[2] / Dc;

    cudaFuncSetAttribute(edge_kernel, cudaFuncAttributeMaxDynamicSharedMemorySize, SMEM_EDGE);
    cudaFuncSetAttribute(node_kernel, cudaFuncAttributeMaxDynamicSharedMemorySize, SMEM_NODE);

    int zero_grid = (N * (Dc / 4) + 255) / 256;
    zero_kernel<<<zero_grid, 256>>>(N);

    prep_kernel<<<8, 256>>>(W1, W2, W3, W4);

    int nblk_e = (E + 15) / 16;
    edge_kernel<<<EDGE_GRID, 256, SMEM_EDGE>>>(bf, eh, nh, src, dst, b1, b2, E, nblk_e);

    int nblk_n = (N + 15) / 16;
    node_kernel<<<EDGE_GRID, 256, SMEM_NODE>>>(b3, b4, (float*)d_out, N, nblk_n);
}

// round 16
// speedup vs baseline: 1.4217x; 1.0378x over previous
#include <cuda_runtime.h>
#include <cuda_bf16.h>
#include <cstdint>
#include <math.h>

// ---------------------------------------------------------------------------
// SchnetConv — persistent mma edge+node kernels (bf16 hi/lo 3-term, fast ssp,
// per-warp streams) with REGISTER-RESIDENT GEMM1->GEMM2 handoff: the D-
// accumulator layout of GEMM1 equals the A-fragment layout of GEMM2, so the
// SMEM strip round trip (STS + syncwarp + ldmatrix) is eliminated.
// ---------------------------------------------------------------------------

#define Dc       64
#define Rc       128
#define N_MAX    100000
#define EDGE_GRID 296      // 2 CTAs/SM x 148 SMs

__device__ float g_s[(size_t)N_MAX * Dc];
__device__ float g_cnt[N_MAX];
// fragment-ordered weight image (uint4{hix,hiy,lox,loy} per (ks,nt,lane)):
// B1 [8ks][8nt][32] = 32KB | B2 [4ks][8nt][32] = 16KB | B3 = 16KB | B4 = 16KB
__device__ __align__(16) unsigned char g_Bimg[81920];

// edge SMEM layout (bytes)
#define OFF_B1    0
#define OFF_B2    32768
#define OFF_BIAS  49152     // b1[64], b2[64]
#define SMEM_EDGE 49664

// node SMEM layout (bytes)
#define NOFF_B3    0
#define NOFF_B4    16384
#define NOFF_BIAS  32768    // b3[64], b4[64]
#define SMEM_NODE  33280

// ---- helpers ---------------------------------------------------------------
__device__ __forceinline__ float ssp_f(float x) {
    float e = __expf(-fabsf(x));
    return fmaxf(x, 0.0f) + __logf(1.0f + e) - 0.69314718055994531f;
}
__device__ __forceinline__ uint32_t smem_u32(const void* p) {
    uint32_t a;
    asm("{ .reg .u64 t; cvta.to.shared.u64 t, %1; cvt.u32.u64 %0, t; }" : "=r"(a) : "l"(p));
    return a;
}
// x = hi + lo (bf16 each); packs (x0 -> low half, x1 -> high half)
__device__ __forceinline__ void split2(float x0, float x1, uint32_t& hi, uint32_t& lo) {
    asm("cvt.rn.bf16x2.f32 %0, %1, %2;" : "=r"(hi) : "f"(x1), "f"(x0));
    float h0 = __uint_as_float(hi << 16);
    float h1 = __uint_as_float(hi & 0xffff0000u);
    asm("cvt.rn.bf16x2.f32 %0, %1, %2;" : "=r"(lo) : "f"(x1 - h1), "f"(x0 - h0));
}
__device__ __forceinline__ void mma16816(float* c, const uint32_t* a, uint32_t b0, uint32_t b1) {
    asm volatile(
        "mma.sync.aligned.m16n8k16.row.col.f32.bf16.bf16.f32 "
        "{%0,%1,%2,%3}, {%4,%5,%6,%7}, {%8,%9}, {%0,%1,%2,%3};"
        : "+f"(c[0]), "+f"(c[1]), "+f"(c[2]), "+f"(c[3])
        : "r"(a[0]), "r"(a[1]), "r"(a[2]), "r"(a[3]), "r"(b0), "r"(b1));
}

// ---------------------------------------------------------------------------
__global__ void zero_kernel(int n_nodes) {
    int i = blockIdx.x * 256 + threadIdx.x;
    int t4 = n_nodes * (Dc / 4);
    if (i < t4) ((float4*)g_s)[i] = make_float4(0.f, 0.f, 0.f, 0.f);
    if (i < n_nodes) g_cnt[i] = 0.0f;
}

// Build fragment-ordered hi/lo weight images for W1/W2/W3/W4.
__global__ void prep_kernel(const float* __restrict__ W1, const float* __restrict__ W2,
                            const float* __restrict__ W3, const float* __restrict__ W4) {
    int i = blockIdx.x * 256 + threadIdx.x;
    if (i < 2048) {   // B1: idx = (ks*8+nt)*32+lane
        int lane = i & 31, nt = (i >> 5) & 7, ks = i >> 8;
        int tid4 = lane & 3, g = lane >> 2;
        int k0 = ks * 16 + tid4 * 2;
        int n  = nt * 8 + g;
        float e00 = W1[(k0    ) * Dc + n], e01 = W1[(k0 + 1) * Dc + n];
        float e10 = W1[(k0 + 8) * Dc + n], e11 = W1[(k0 + 9) * Dc + n];
        uint32_t hx, lx, hy, ly;
        split2(e00, e01, hx, lx);
        split2(e10, e11, hy, ly);
        uint4 v; v.x = hx; v.y = hy; v.z = lx; v.w = ly;
        ((uint4*)g_Bimg)[i] = v;
    }
    if (i < 1024) {   // B2 / B3 / B4 (all 64x64)
        int lane = i & 31, nt = (i >> 5) & 7, ks = i >> 8;
        int tid4 = lane & 3, g = lane >> 2;
        int k0 = ks * 16 + tid4 * 2;
        int n  = nt * 8 + g;
        const float* Ws[3] = {W2, W3, W4};
        unsigned char* dsts[3] = {g_Bimg + 32768, g_Bimg + 49152, g_Bimg + 65536};
#pragma unroll
        for (int m = 0; m < 3; ++m) {
            const float* W = Ws[m];
            float e00 = W[(k0    ) * Dc + n], e01 = W[(k0 + 1) * Dc + n];
            float e10 = W[(k0 + 8) * Dc + n], e11 = W[(k0 + 9) * Dc + n];
            uint32_t hx, lx, hy, ly;
            split2(e00, e01, hx, lx);
            split2(e10, e11, hy, ly);
            uint4 v; v.x = hx; v.y = hy; v.z = lx; v.w = ly;
            ((uint4*)dsts[m])[i] = v;
        }
    }
}

// ---------------------------------------------------------------------------
// Persistent edge kernel: weights staged once, each warp grid-strides over
// 16-edge blocks; GEMM1->GEMM2 handoff entirely in registers.
// ---------------------------------------------------------------------------
__global__ __launch_bounds__(256, 2)
void edge_kernel(const float* __restrict__ bf, const float* __restrict__ eh,
                 const float* __restrict__ nh, const int* __restrict__ src,
                 const int* __restrict__ dst,
                 const float* __restrict__ b1, const float* __restrict__ b2,
                 int E, int nblk)
{
    extern __shared__ unsigned char smx[];
    const int t = threadIdx.x, w = t >> 5, lane = t & 31;
    const int g = lane >> 2, tid4 = lane & 3;

    // one-time stage: weight fragments (48KB) + biases
    {
        const uint4* gi = (const uint4*)g_Bimg;
        uint4* s = (uint4*)smx;
        for (int i = t; i < 3072; i += 256) s[i] = gi[i];
        float* sbias = (float*)(smx + OFF_BIAS);
        if (t < Dc) sbias[t] = b1[t];
        else if (t < 2 * Dc) sbias[t] = b2[t - Dc];
    }
    __syncthreads();

    const float* sb1 = (const float*)(smx + OFF_BIAS);
    const float* sb2 = sb1 + Dc;

    const int gw = blockIdx.x * 8 + w;       // global warp-stream id
    const int nstreams = gridDim.x * 8;

    for (int blk = gw; blk < nblk; blk += nstreams) {
        const int e0 = blk * 16;             // this warp's 16-edge block

        const int er0 = min(e0 + g,     E - 1);
        const int er1 = min(e0 + g + 8, E - 1);
        const bool v0 = (e0 + g)     < E;
        const bool v1 = (e0 + g + 8) < E;
        const float* p0 = bf + (size_t)er0 * Rc;
        const float* p1 = bf + (size_t)er1 * Rc;

        float acc[8][4];
#pragma unroll
        for (int nt = 0; nt < 8; ++nt)
#pragma unroll
            for (int q = 0; q < 4; ++q) acc[nt][q] = 0.f;

        // ---- GEMM1: f1raw = bf @ W1, K=128 (8 k-steps), N=64 (8 n-tiles) ----
#pragma unroll
        for (int ks = 0; ks < 8; ++ks) {
            const int k0 = ks * 16 + tid4 * 2;
            float2 x00 = *(const float2*)(p0 + k0);
            float2 x10 = *(const float2*)(p1 + k0);
            float2 x01 = *(const float2*)(p0 + k0 + 8);
            float2 x11 = *(const float2*)(p1 + k0 + 8);
            uint32_t aH[4], aL[4];
            split2(x00.x, x00.y, aH[0], aL[0]);
            split2(x10.x, x10.y, aH[1], aL[1]);
            split2(x01.x, x01.y, aH[2], aL[2]);
            split2(x11.x, x11.y, aH[3], aL[3]);
            const uint4* Bp = (const uint4*)(smx + OFF_B1) + (ks * 8) * 32 + lane;
#pragma unroll
            for (int nt = 0; nt < 8; ++nt) {
                uint4 bb = Bp[nt * 32];
                mma16816(acc[nt], aH, bb.x, bb.y);   // Ah*Bh
                mma16816(acc[nt], aH, bb.z, bb.w);   // Ah*Bl
                mma16816(acc[nt], aL, bb.x, bb.y);   // Al*Bh
            }
        }

        // ---- register handoff: bias + ssp + split -> GEMM2 A-fragments ----
        // D-layout of acc[2ks] = A-frag regs {r0,r1} (cols 16ks+tid4*2),
        // acc[2ks+1] = {r2,r3} (cols 16ks+8+tid4*2).
        uint32_t a2H[4][4], a2L[4][4];
#pragma unroll
        for (int ks = 0; ks < 4; ++ks)
#pragma unroll
            for (int h = 0; h < 2; ++h) {
                int nt = 2 * ks + h;
                int n = nt * 8 + tid4 * 2;
                float f0 = ssp_f(acc[nt][0] + sb1[n]);
                float f1 = ssp_f(acc[nt][1] + sb1[n + 1]);
                float f2 = ssp_f(acc[nt][2] + sb1[n]);
                float f3 = ssp_f(acc[nt][3] + sb1[n + 1]);
                split2(f0, f1, a2H[ks][2 * h + 0], a2L[ks][2 * h + 0]);
                split2(f2, f3, a2H[ks][2 * h + 1], a2L[ks][2 * h + 1]);
            }
#pragma unroll
        for (int nt = 0; nt < 8; ++nt)
#pragma unroll
            for (int q = 0; q < 4; ++q) acc[nt][q] = 0.f;

        // ---- GEMM2: f2raw = f1 @ W2, K=64 (4 k-steps) ----
#pragma unroll
        for (int ks = 0; ks < 4; ++ks) {
            const uint4* Bp = (const uint4*)(smx + OFF_B2) + (ks * 8) * 32 + lane;
#pragma unroll
            for (int nt = 0; nt < 8; ++nt) {
                uint4 bb = Bp[nt * 32];
                mma16816(acc[nt], a2H[ks], bb.x, bb.y);
                mma16816(acc[nt], a2H[ks], bb.z, bb.w);
                mma16816(acc[nt], a2L[ks], bb.x, bb.y);
            }
        }

        // ---- epilogue: m = f2 * eh * nh[src]; red.global.v2 to g_s ----
        int sv0 = 0, dv0 = 0, sv1 = 0, dv1 = 0;
        if (v0) { sv0 = src[e0 + g];     dv0 = dst[e0 + g]; }
        if (v1) { sv1 = src[e0 + g + 8]; dv1 = dst[e0 + g + 8]; }
        if (tid4 == 0) {
            if (v0) atomicAdd(&g_cnt[dv0], 1.0f);
            if (v1) atomicAdd(&g_cnt[dv1], 1.0f);
        }
#pragma unroll
        for (int nt = 0; nt < 8; ++nt) {
            int n = nt * 8 + tid4 * 2;
            if (v0) {
                float f0 = ssp_f(acc[nt][0] + sb2[n]);
                float f1 = ssp_f(acc[nt][1] + sb2[n + 1]);
                float2 ev = *(const float2*)&eh[(size_t)(e0 + g) * Dc + n];
                float2 nv = *(const float2*)&nh[(size_t)sv0 * Dc + n];
                float m0 = f0 * ev.x * nv.x;
                float m1 = f1 * ev.y * nv.y;
                float* gp = &g_s[(size_t)dv0 * Dc + n];
                asm volatile("red.global.add.v2.f32 [%0], {%1, %2};"
                             :: "l"(gp), "f"(m0), "f"(m1) : "memory");
            }
            if (v1) {
                float f2 = ssp_f(acc[nt][2] + sb2[n]);
                float f3 = ssp_f(acc[nt][3] + sb2[n + 1]);
                float2 ev = *(const float2*)&eh[(size_t)(e0 + g + 8) * Dc + n];
                float2 nv = *(const float2*)&nh[(size_t)sv1 * Dc + n];
                float m2 = f2 * ev.x * nv.x;
                float m3 = f3 * ev.y * nv.y;
                float* gp = &g_s[(size_t)dv1 * Dc + n];
                asm volatile("red.global.add.v2.f32 [%0], {%1, %2};"
                             :: "l"(gp), "f"(m2), "f"(m3) : "memory");
            }
        }
    }
}

// ---------------------------------------------------------------------------
// Persistent mma node kernel: agg = g_s*inv_cnt -> MLP3 -> MLP4 -> out.
// Register-resident GEMM3->GEMM4 handoff, per-warp 16-node streams.
// ---------------------------------------------------------------------------
__global__ __launch_bounds__(256, 2)
void node_kernel(const float* __restrict__ b3, const float* __restrict__ b4,
                 float* __restrict__ out, int N, int nblk)
{
    extern __shared__ unsigned char smx[];
    const int t = threadIdx.x, w = t >> 5, lane = t & 31;
    const int g = lane >> 2, tid4 = lane & 3;

    // one-time stage: B3/B4 fragments (32KB) + biases
    {
        const uint4* gi = (const uint4*)(g_Bimg + 49152);
        uint4* s = (uint4*)smx;
        for (int i = t; i < 2048; i += 256) s[i] = gi[i];
        float* sbias = (float*)(smx + NOFF_BIAS);
        if (t < Dc) sbias[t] = b3[t];
        else if (t < 2 * Dc) sbias[t] = b4[t - Dc];
    }
    __syncthreads();

    const float* sb3 = (const float*)(smx + NOFF_BIAS);
    const float* sb4 = sb3 + Dc;

    const int gw = blockIdx.x * 8 + w;
    const int nstreams = gridDim.x * 8;

    for (int blk = gw; blk < nblk; blk += nstreams) {
        const int n0r = blk * 16;

        const int nr0 = min(n0r + g,     N - 1);
        const int nr1 = min(n0r + g + 8, N - 1);
        const bool v0 = (n0r + g)     < N;
        const bool v1 = (n0r + g + 8) < N;
        const float* p0 = g_s + (size_t)nr0 * Dc;
        const float* p1 = g_s + (size_t)nr1 * Dc;
        float c0 = g_cnt[nr0], c1 = g_cnt[nr1];
        const float inv0 = (c0 > 0.0f) ? (1.0f / c0) : 0.0f;
        const float inv1 = (c1 > 0.0f) ? (1.0f / c1) : 0.0f;

        float acc[8][4];
#pragma unroll
        for (int nt = 0; nt < 8; ++nt)
#pragma unroll
            for (int q = 0; q < 4; ++q) acc[nt][q] = 0.f;

        // ---- GEMM3: h1raw = agg @ W3, K=64 (4 k-steps) ----
#pragma unroll
        for (int ks = 0; ks < 4; ++ks) {
            const int k0 = ks * 16 + tid4 * 2;
            float2 x00 = *(const float2*)(p0 + k0);
            float2 x10 = *(const float2*)(p1 + k0);
            float2 x01 = *(const float2*)(p0 + k0 + 8);
            float2 x11 = *(const float2*)(p1 + k0 + 8);
            uint32_t aH[4], aL[4];
            split2(x00.x * inv0, x00.y * inv0, aH[0], aL[0]);
            split2(x10.x * inv1, x10.y * inv1, aH[1], aL[1]);
            split2(x01.x * inv0, x01.y * inv0, aH[2], aL[2]);
            split2(x11.x * inv1, x11.y * inv1, aH[3], aL[3]);
            const uint4* Bp = (const uint4*)(smx + NOFF_B3) + (ks * 8) * 32 + lane;
#pragma unroll
            for (int nt = 0; nt < 8; ++nt) {
                uint4 bb = Bp[nt * 32];
                mma16816(acc[nt], aH, bb.x, bb.y);
                mma16816(acc[nt], aH, bb.z, bb.w);
                mma16816(acc[nt], aL, bb.x, bb.y);
            }
        }

        // ---- register handoff: bias + ssp + split -> GEMM4 A-fragments ----
        uint32_t a2H[4][4], a2L[4][4];
#pragma unroll
        for (int ks = 0; ks < 4; ++ks)
#pragma unroll
            for (int h = 0; h < 2; ++h) {
                int nt = 2 * ks + h;
                int n = nt * 8 + tid4 * 2;
                float f0 = ssp_f(acc[nt][0] + sb3[n]);
                float f1 = ssp_f(acc[nt][1] + sb3[n + 1]);
                float f2 = ssp_f(acc[nt][2] + sb3[n]);
                float f3 = ssp_f(acc[nt][3] + sb3[n + 1]);
                split2(f0, f1, a2H[ks][2 * h + 0], a2L[ks][2 * h + 0]);
                split2(f2, f3, a2H[ks][2 * h + 1], a2L[ks][2 * h + 1]);
            }
#pragma unroll
        for (int nt = 0; nt < 8; ++nt)
#pragma unroll
            for (int q = 0; q < 4; ++q) acc[nt][q] = 0.f;

        // ---- GEMM4: outraw = h1 @ W4, K=64 (4 k-steps) ----
#pragma unroll
        for (int ks = 0; ks < 4; ++ks) {
            const uint4* Bp = (const uint4*)(smx + NOFF_B4) + (ks * 8) * 32 + lane;
#pragma unroll
            for (int nt = 0; nt < 8; ++nt) {
                uint4 bb = Bp[nt * 32];
                mma16816(acc[nt], a2H[ks], bb.x, bb.y);
                mma16816(acc[nt], a2H[ks], bb.z, bb.w);
                mma16816(acc[nt], a2L[ks], bb.x, bb.y);
            }
        }

        // ---- epilogue: out = ssp(acc + b4), float2 stores ----
#pragma unroll
        for (int nt = 0; nt < 8; ++nt) {
            int n = nt * 8 + tid4 * 2;
            if (v0) {
                float2 o;
                o.x = ssp_f(acc[nt][0] + sb4[n]);
                o.y = ssp_f(acc[nt][1] + sb4[n + 1]);
                *(float2*)&out[(size_t)(n0r + g) * Dc + n] = o;
            }
            if (v1) {
                float2 o;
                o.x = ssp_f(acc[nt][2] + sb4[n]);
                o.y = ssp_f(acc[nt][3] + sb4[n + 1]);
                *(float2*)&out[(size_t)(n0r + g + 8) * Dc + n] = o;
            }
        }
    }
}

// ---------------------------------------------------------------------------
extern "C" void kernel_launch(void* const* d_in, const int* in_sizes, int n_in,
                              void* d_out, int out_size)
{
    const float* bf  = (const float*)d_in[0];
    const float* eh  = (const float*)d_in[1];
    const float* nh  = (const float*)d_in[2];
    const int*   src = (const int*)  d_in[3];
    const int*   dst = (const int*)  d_in[4];
    const float* W1  = (const float*)d_in[5];
    const float* b1  = (const float*)d_in[6];
    const float* W2  = (const float*)d_in[7];
    const float* b2  = (const float*)d_in[8];
    const float* W3  = (const float*)d_in[9];
    const float* b3  = (const float*)d_in[10];
    const float* W4  = (const float*)d_in[11];
    const float* b4  = (const float*)d_in[12];

    int E = in_sizes[3];
    int N = in_sizes[2] / Dc;

    cudaFuncSetAttribute(edge_kernel, cudaFuncAttributeMaxDynamicSharedMemorySize, SMEM_EDGE);
    cudaFuncSetAttribute(node_kernel, cudaFuncAttributeMaxDynamicSharedMemorySize, SMEM_NODE);

    int zero_grid = (N * (Dc / 4) + 255) / 256;
    zero_kernel<<<zero_grid, 256>>>(N);

    prep_kernel<<<8, 256>>>(W1, W2, W3, W4);

    int nblk_e = (E + 15) / 16;
    edge_kernel<<<EDGE_GRID, 256, SMEM_EDGE>>>(bf, eh, nh, src, dst, b1, b2, E, nblk_e);

    int nblk_n = (N + 15) / 16;
    node_kernel<<<EDGE_GRID, 256, SMEM_NODE>>>(b3, b4, (float*)d_out, N, nblk_n);
}